// round 1
// baseline (speedup 1.0000x reference)
#include <cuda_runtime.h>

#define N_B 32
#define T_S 2048
#define D_E 1024
#define U_D 1024

#define BM 128
#define BN 128
#define BK 16
#define KT (D_E / BK)   // 64 k-tiles

// Scratch (device globals: no allocation allowed in kernel_launch)
__device__ float g_pq[N_B * U_D];        // proj_query [32,1024]
__device__ float g_weights[N_B * T_S];   // logits     [32,2048]

// ---------------------------------------------------------------------------
// Zero the logit accumulator (atomically accumulated across u-tiles).
// ---------------------------------------------------------------------------
__global__ void zero_weights_kernel() {
    int i = blockIdx.x * blockDim.x + threadIdx.x;
    if (i < N_B * T_S) g_weights[i] = 0.f;
}

// ---------------------------------------------------------------------------
// pq[n,u] = dot(queries[n,:], Wq[u,:])   (one warp per output element)
// ---------------------------------------------------------------------------
__global__ void pq_kernel(const float* __restrict__ q, const float* __restrict__ Wq) {
    int wid  = (blockIdx.x * blockDim.x + threadIdx.x) >> 5;
    int lane = threadIdx.x & 31;
    if (wid >= N_B * U_D) return;
    int n = wid >> 10;
    int u = wid & 1023;
    const float4* q4 = (const float4*)(q + (size_t)n * D_E);
    const float4* w4 = (const float4*)(Wq + (size_t)u * D_E);
    float s = 0.f;
    for (int i = lane; i < D_E / 4; i += 32) {
        float4 a = q4[i], b = w4[i];
        s += a.x * b.x + a.y * b.y + a.z * b.z + a.w * b.w;
    }
    #pragma unroll
    for (int o = 16; o > 0; o >>= 1) s += __shfl_down_sync(0xffffffffu, s, o);
    if (lane == 0) g_pq[wid] = s;
}

// ---------------------------------------------------------------------------
// Fused logits GEMM: for block (t_tile, n, u_tile):
//   C[128x128] = enc[n, t0:t0+128, :] @ Wk[u0:u0+128, :]^T   (fp32, K=1024)
//   logits[n, t] += sum_j v[u] * tanh(C[t][u] + pq[n,u])
// Blocks whose whole t-tile is masked (t0 >= lengths[n]) exit immediately.
// ---------------------------------------------------------------------------
__global__ void __launch_bounds__(256, 2)
weights_kernel(const float* __restrict__ enc, const float* __restrict__ Wk,
               const float* __restrict__ v, const int* __restrict__ lengths) {
    int n  = blockIdx.y;
    int t0 = blockIdx.x * BM;
    int u0 = blockIdx.z * BN;
    if (t0 >= lengths[n]) return;

    __shared__ __align__(16) float As[2][BK][BM];
    __shared__ __align__(16) float Bs[2][BK][BN];
    __shared__ float wpart[BM];

    const float* A = enc + ((size_t)n * T_S + t0) * D_E;   // [128,1024] row-major
    const float* B = Wk + (size_t)u0 * D_E;                // [128,1024] row-major

    int tid  = threadIdx.x;
    int lrow = tid >> 1;          // 0..127 : row loaded by this thread
    int lk   = (tid & 1) * 8;     // 0 or 8 : k offset (two float4 per thread)

    int tr = (tid >> 4) * 8;      // output row offset (0..120)
    int tc = (tid & 15) * 8;      // output col offset (0..120)

    float acc[8][8];
    #pragma unroll
    for (int i = 0; i < 8; i++)
        #pragma unroll
        for (int j = 0; j < 8; j++) acc[i][j] = 0.f;

    // preload k-tile 0
    {
        float4 a0 = *(const float4*)(A + (size_t)lrow * D_E + lk);
        float4 a1 = *(const float4*)(A + (size_t)lrow * D_E + lk + 4);
        float4 b0 = *(const float4*)(B + (size_t)lrow * D_E + lk);
        float4 b1 = *(const float4*)(B + (size_t)lrow * D_E + lk + 4);
        As[0][lk + 0][lrow] = a0.x; As[0][lk + 1][lrow] = a0.y;
        As[0][lk + 2][lrow] = a0.z; As[0][lk + 3][lrow] = a0.w;
        As[0][lk + 4][lrow] = a1.x; As[0][lk + 5][lrow] = a1.y;
        As[0][lk + 6][lrow] = a1.z; As[0][lk + 7][lrow] = a1.w;
        Bs[0][lk + 0][lrow] = b0.x; Bs[0][lk + 1][lrow] = b0.y;
        Bs[0][lk + 2][lrow] = b0.z; Bs[0][lk + 3][lrow] = b0.w;
        Bs[0][lk + 4][lrow] = b1.x; Bs[0][lk + 5][lrow] = b1.y;
        Bs[0][lk + 6][lrow] = b1.z; Bs[0][lk + 7][lrow] = b1.w;
    }
    __syncthreads();

    int buf = 0;
    for (int kt = 0; kt < KT; kt++) {
        float4 a0, a1, b0, b1;
        bool pf = (kt + 1 < KT);
        if (pf) {
            const float* Ak = A + (size_t)(kt + 1) * BK;
            const float* Bk = B + (size_t)(kt + 1) * BK;
            a0 = *(const float4*)(Ak + (size_t)lrow * D_E + lk);
            a1 = *(const float4*)(Ak + (size_t)lrow * D_E + lk + 4);
            b0 = *(const float4*)(Bk + (size_t)lrow * D_E + lk);
            b1 = *(const float4*)(Bk + (size_t)lrow * D_E + lk + 4);
        }
        #pragma unroll
        for (int k = 0; k < BK; k++) {
            float ar[8], br[8];
            *(float4*)&ar[0] = *(const float4*)&As[buf][k][tr];
            *(float4*)&ar[4] = *(const float4*)&As[buf][k][tr + 4];
            *(float4*)&br[0] = *(const float4*)&Bs[buf][k][tc];
            *(float4*)&br[4] = *(const float4*)&Bs[buf][k][tc + 4];
            #pragma unroll
            for (int i = 0; i < 8; i++)
                #pragma unroll
                for (int j = 0; j < 8; j++)
                    acc[i][j] += ar[i] * br[j];
        }
        if (pf) {
            int nb = buf ^ 1;
            As[nb][lk + 0][lrow] = a0.x; As[nb][lk + 1][lrow] = a0.y;
            As[nb][lk + 2][lrow] = a0.z; As[nb][lk + 3][lrow] = a0.w;
            As[nb][lk + 4][lrow] = a1.x; As[nb][lk + 5][lrow] = a1.y;
            As[nb][lk + 6][lrow] = a1.z; As[nb][lk + 7][lrow] = a1.w;
            Bs[nb][lk + 0][lrow] = b0.x; Bs[nb][lk + 1][lrow] = b0.y;
            Bs[nb][lk + 2][lrow] = b0.z; Bs[nb][lk + 3][lrow] = b0.w;
            Bs[nb][lk + 4][lrow] = b1.x; Bs[nb][lk + 5][lrow] = b1.y;
            Bs[nb][lk + 6][lrow] = b1.z; Bs[nb][lk + 7][lrow] = b1.w;
        }
        __syncthreads();
        buf ^= 1;
    }

    // epilogue: s[row] = sum_j v[u] * tanh(acc + pq[n,u]), reduce, accumulate
    float pqv[8], vv[8];
    #pragma unroll
    for (int j = 0; j < 8; j++) {
        int u = u0 + tc + j;
        pqv[j] = g_pq[n * U_D + u];
        vv[j]  = v[u];
    }
    if (tid < BM) wpart[tid] = 0.f;
    __syncthreads();
    #pragma unroll
    for (int i = 0; i < 8; i++) {
        float s = 0.f;
        #pragma unroll
        for (int j = 0; j < 8; j++)
            s += vv[j] * tanhf(acc[i][j] + pqv[j]);
        atomicAdd(&wpart[tr + i], s);
    }
    __syncthreads();
    if (tid < BM)
        atomicAdd(&g_weights[n * T_S + t0 + tid], wpart[tid]);
}

// ---------------------------------------------------------------------------
// Masked softmax over t in [0, len); masked positions get exactly 0.
// ---------------------------------------------------------------------------
__global__ void softmax_kernel(const int* __restrict__ lengths,
                               float* __restrict__ align) {
    int n   = blockIdx.x;
    int len = lengths[n];
    int tid = threadIdx.x;   // 256 threads
    const float* w = g_weights + n * T_S;
    __shared__ float sm[256];

    float m = -1e30f;
    for (int t = tid; t < len; t += 256) m = fmaxf(m, w[t]);
    sm[tid] = m; __syncthreads();
    for (int s = 128; s > 0; s >>= 1) {
        if (tid < s) sm[tid] = fmaxf(sm[tid], sm[tid + s]);
        __syncthreads();
    }
    m = sm[0]; __syncthreads();

    float sum = 0.f;
    for (int t = tid; t < len; t += 256) sum += expf(w[t] - m);
    sm[tid] = sum; __syncthreads();
    for (int s = 128; s > 0; s >>= 1) {
        if (tid < s) sm[tid] += sm[tid + s];
        __syncthreads();
    }
    float inv = 1.f / sm[0];

    for (int t = tid; t < T_S; t += 256)
        align[(size_t)n * T_S + t] = (t < len) ? expf(w[t] - m) * inv : 0.f;
}

// ---------------------------------------------------------------------------
// contexts[n,e] = sum_{t<len} align[n,t] * enc[n,t,e]
// ---------------------------------------------------------------------------
__global__ void context_kernel(const float* __restrict__ enc,
                               const int* __restrict__ lengths,
                               const float* __restrict__ align,
                               float* __restrict__ ctx) {
    int n   = blockIdx.y;
    int e   = blockIdx.x * 256 + threadIdx.x;
    int len = lengths[n];
    const float* al = align + (size_t)n * T_S;
    const float* E  = enc + (size_t)n * T_S * D_E + e;
    float c0 = 0.f, c1 = 0.f, c2 = 0.f, c3 = 0.f;
    int t = 0;
    for (; t + 4 <= len; t += 4) {
        c0 += al[t + 0] * E[(size_t)(t + 0) * D_E];
        c1 += al[t + 1] * E[(size_t)(t + 1) * D_E];
        c2 += al[t + 2] * E[(size_t)(t + 2) * D_E];
        c3 += al[t + 3] * E[(size_t)(t + 3) * D_E];
    }
    for (; t < len; t++) c0 += al[t] * E[(size_t)t * D_E];
    ctx[(size_t)n * D_E + e] = (c0 + c1) + (c2 + c3);
}

// ---------------------------------------------------------------------------
extern "C" void kernel_launch(void* const* d_in, const int* in_sizes, int n_in,
                              void* d_out, int out_size) {
    const float* q       = (const float*)d_in[0];  // [32,1,1024]
    const float* enc     = (const float*)d_in[1];  // [32,2048,1024]
    const int*   lengths = (const int*)  d_in[2];  // [32]
    const float* v       = (const float*)d_in[3];  // [1024]
    const float* Wq      = (const float*)d_in[4];  // [1024,1024]
    const float* Wk      = (const float*)d_in[5];  // [1024,1024]

    float* out   = (float*)d_out;
    float* ctx   = out;                 // contexts   [32,1024]
    float* align = out + N_B * D_E;     // alignments [32,2048]

    zero_weights_kernel<<<(N_B * T_S + 255) / 256, 256>>>();
    pq_kernel<<<(N_B * U_D) / 8, 256>>>(q, Wq);   // 8 warps/block, 1 warp/output

    dim3 g(T_S / BM, N_B, U_D / BN);              // (16, 32, 8)
    weights_kernel<<<g, 256>>>(enc, Wk, v, lengths);

    softmax_kernel<<<N_B, 256>>>(lengths, align);

    dim3 gc(D_E / 256, N_B);                      // (4, 32)
    context_kernel<<<gc, 256>>>(enc, lengths, align, ctx);
}

// round 3
// speedup vs baseline: 1.9468x; 1.9468x over previous
#include <cuda_runtime.h>
#include <cuda_fp16.h>
#include <cstdint>

#define N_B 32
#define T_S 2048
#define D_E 1024
#define U_D 1024

// Scratch (device globals: no allocation allowed)
__device__ float g_pq[N_B * U_D];        // proj_query [32,1024]
__device__ float g_weights[N_B * T_S];   // logits     [32,2048]

// ===========================================================================
// Helpers
// ===========================================================================
__device__ __forceinline__ uint32_t smem_u32(const void* p) {
    uint32_t a;
    asm("{ .reg .u64 t; cvta.to.shared.u64 t, %1; cvt.u32.u64 %0, t; }"
        : "=r"(a) : "l"(p));
    return a;
}
__device__ __forceinline__ void ldm4(uint32_t* r, uint32_t addr) {
    asm volatile("ldmatrix.sync.aligned.m8n8.x4.shared.b16 {%0,%1,%2,%3}, [%4];"
                 : "=r"(r[0]), "=r"(r[1]), "=r"(r[2]), "=r"(r[3]) : "r"(addr));
}
__device__ __forceinline__ void mma16816(float* c, const uint32_t* a,
                                         const uint32_t* b) {
    asm volatile(
        "mma.sync.aligned.m16n8k16.row.col.f32.f16.f16.f32 "
        "{%0,%1,%2,%3}, {%4,%5,%6,%7}, {%8,%9}, {%0,%1,%2,%3};"
        : "+f"(c[0]), "+f"(c[1]), "+f"(c[2]), "+f"(c[3])
        : "r"(a[0]), "r"(a[1]), "r"(a[2]), "r"(a[3]), "r"(b[0]), "r"(b[1]));
}
// fp32 pair -> (hi fp16x2, lo fp16x2)
__device__ __forceinline__ void cvt2(float x, float y, uint32_t& hi, uint32_t& lo) {
    __half2 h = __floats2half2_rn(x, y);
    float2 hf = __half22float2(h);
    __half2 l = __floats2half2_rn(x - hf.x, y - hf.y);
    hi = *(uint32_t*)&h;
    lo = *(uint32_t*)&l;
}
__device__ __forceinline__ void sts128(uint32_t addr, uint32_t a, uint32_t b,
                                       uint32_t c, uint32_t d) {
    asm volatile("st.shared.v4.b32 [%0], {%1,%2,%3,%4};"
                 :: "r"(addr), "r"(a), "r"(b), "r"(c), "r"(d) : "memory");
}

// ===========================================================================
// Simple kernels
// ===========================================================================
__global__ void zero_weights_kernel() {
    int i = blockIdx.x * blockDim.x + threadIdx.x;
    if (i < N_B * T_S) g_weights[i] = 0.f;
}

__global__ void pq_kernel(const float* __restrict__ q, const float* __restrict__ Wq) {
    int wid  = (blockIdx.x * blockDim.x + threadIdx.x) >> 5;
    int lane = threadIdx.x & 31;
    if (wid >= N_B * U_D) return;
    int n = wid >> 10;
    int u = wid & 1023;
    const float4* q4 = (const float4*)(q + (size_t)n * D_E);
    const float4* w4 = (const float4*)(Wq + (size_t)u * D_E);
    float s = 0.f;
    for (int i = lane; i < D_E / 4; i += 32) {
        float4 a = q4[i], b = w4[i];
        s += a.x * b.x + a.y * b.y + a.z * b.z + a.w * b.w;
    }
    #pragma unroll
    for (int o = 16; o > 0; o >>= 1) s += __shfl_down_sync(0xffffffffu, s, o);
    if (lane == 0) g_pq[wid] = s;
}

__global__ void softmax_kernel(const int* __restrict__ lengths,
                               float* __restrict__ align) {
    int n   = blockIdx.x;
    int len = lengths[n];
    int tid = threadIdx.x;
    const float* w = g_weights + n * T_S;
    __shared__ float sm[256];

    float m = -1e30f;
    for (int t = tid; t < len; t += 256) m = fmaxf(m, w[t]);
    sm[tid] = m; __syncthreads();
    for (int s = 128; s > 0; s >>= 1) {
        if (tid < s) sm[tid] = fmaxf(sm[tid], sm[tid + s]);
        __syncthreads();
    }
    m = sm[0]; __syncthreads();

    float sum = 0.f;
    for (int t = tid; t < len; t += 256) sum += expf(w[t] - m);
    sm[tid] = sum; __syncthreads();
    for (int s = 128; s > 0; s >>= 1) {
        if (tid < s) sm[tid] += sm[tid + s];
        __syncthreads();
    }
    float inv = 1.f / sm[0];

    for (int t = tid; t < T_S; t += 256)
        align[(size_t)n * T_S + t] = (t < len) ? expf(w[t] - m) * inv : 0.f;
}

__global__ void context_kernel(const float* __restrict__ enc,
                               const int* __restrict__ lengths,
                               const float* __restrict__ align,
                               float* __restrict__ ctx) {
    int n   = blockIdx.y;
    int e   = blockIdx.x * 256 + threadIdx.x;
    int len = lengths[n];
    const float* al = align + (size_t)n * T_S;
    const float* E  = enc + (size_t)n * T_S * D_E + e;
    float c0 = 0.f, c1 = 0.f, c2 = 0.f, c3 = 0.f;
    int t = 0;
    for (; t + 4 <= len; t += 4) {
        c0 += al[t + 0] * E[(size_t)(t + 0) * D_E];
        c1 += al[t + 1] * E[(size_t)(t + 1) * D_E];
        c2 += al[t + 2] * E[(size_t)(t + 2) * D_E];
        c3 += al[t + 3] * E[(size_t)(t + 3) * D_E];
    }
    for (; t < len; t++) c0 += al[t] * E[(size_t)t * D_E];
    ctx[(size_t)n * D_E + e] = (c0 + c1) + (c2 + c3);
}

// ===========================================================================
// mma.sync 3xFP16-split fused logits GEMM
//   C[128(t) x 128(u)] = enc_tile @ Wk_tile^T  (K=1024, fp32 via hi/lo fp16)
//   logits[n,t] += sum_u v[u]*tanh(C + pq[n,u])
// ===========================================================================
#define BKF     64                    // fp32 K elems per chunk
#define NKC     (D_E / BKF)           // 16 chunks
#define BUF_B   16384                 // 128 rows * 64 halves * 2B
#define OFF_AH  0
#define OFF_AL  16384
#define OFF_BH  32768
#define OFF_BL  49152
#define STAGE_B 65536
#define DYN_SMEM (2 * STAGE_B)

__global__ void __launch_bounds__(512, 1)
weights_tc_kernel(const float* __restrict__ enc, const float* __restrict__ Wk,
                  const float* __restrict__ v, const int* __restrict__ lengths) {
    int n  = blockIdx.z;
    int t0 = blockIdx.y * 128;
    int u0 = blockIdx.x * 128;
    int len = lengths[n];
    if (t0 >= len) return;

    extern __shared__ char dyn_smem[];
    __shared__ float wpart[128];
    uint32_t base = smem_u32(dyn_smem);

    int tid  = threadIdx.x;
    int wid  = tid >> 5;
    int lane = tid & 31;
    int warp_m = wid >> 2;          // 0..3  -> 32-row band
    int warp_n = wid & 3;           // 0..3  -> 32-col band
    int mr0 = warp_m * 32;
    int nc0 = warp_n * 32;

    // ldmatrix per-thread geometry
    int rA  = lane & 15;            // A: rows 0..15 within 16-row tile
    int kgA = lane >> 4;            // A: k-group 0/1 (8-half units)
    int swA = rA & 7;
    int rB  = (lane & 7) | ((lane >> 4) << 3);  // B: row within 16-row pair
    int kgB = (lane >> 3) & 1;
    int swB = rB & 7;

    // Loader geometry: 4 threads per row, 16 floats each
    int arow = tid >> 2;            // 0..127
    int acol = (tid & 3) * 16;      // 0,16,32,48
    const float* Ag = enc + ((size_t)n * T_S + t0 + arow) * D_E + acol;
    const float* Bg = Wk + ((size_t)(u0 + arow)) * D_E + acol;
    // swizzled store base (row*128 bytes; group rotated by row&7)
    uint32_t strow = (uint32_t)arow * 128;
    int g0 = (tid & 3) * 2;

    float c[2][4][4];
    #pragma unroll
    for (int mi = 0; mi < 2; mi++)
        #pragma unroll
        for (int ni = 0; ni < 4; ni++)
            #pragma unroll
            for (int k = 0; k < 4; k++) c[mi][ni][k] = 0.f;

    float4 fa[4], fb[4];

    // ---- prologue: chunk 0 ----
    #pragma unroll
    for (int q = 0; q < 4; q++) {
        fa[q] = *(const float4*)(Ag + q * 4);
        fb[q] = *(const float4*)(Bg + q * 4);
    }
    {
        uint32_t st = base;
        #pragma unroll
        for (int p = 0; p < 2; p++) {
            uint32_t h0, l0, h1, l1, h2, l2, h3, l3;
            cvt2(fa[2*p].x, fa[2*p].y, h0, l0);
            cvt2(fa[2*p].z, fa[2*p].w, h1, l1);
            cvt2(fa[2*p+1].x, fa[2*p+1].y, h2, l2);
            cvt2(fa[2*p+1].z, fa[2*p+1].w, h3, l3);
            uint32_t sg = (uint32_t)(((g0 + p) ^ (arow & 7)) << 4);
            sts128(base + OFF_AH + strow + sg, h0, h1, h2, h3);
            sts128(base + OFF_AL + strow + sg, l0, l1, l2, l3);
            cvt2(fb[2*p].x, fb[2*p].y, h0, l0);
            cvt2(fb[2*p].z, fb[2*p].w, h1, l1);
            cvt2(fb[2*p+1].x, fb[2*p+1].y, h2, l2);
            cvt2(fb[2*p+1].z, fb[2*p+1].w, h3, l3);
            sts128(base + OFF_BH + strow + sg, h0, h1, h2, h3);
            sts128(base + OFF_BL + strow + sg, l0, l1, l2, l3);
        }
        (void)st;
    }
    __syncthreads();

    for (int kc = 0; kc < NKC; kc++) {
        if (kc + 1 < NKC) {
            const float* ga = Ag + (size_t)(kc + 1) * BKF;
            const float* gb = Bg + (size_t)(kc + 1) * BKF;
            #pragma unroll
            for (int q = 0; q < 4; q++) {
                fa[q] = *(const float4*)(ga + q * 4);
                fb[q] = *(const float4*)(gb + q * 4);
            }
        }

        // ---- compute chunk kc ----
        uint32_t st  = base + (uint32_t)(kc & 1) * STAGE_B;
        uint32_t aAH = st + OFF_AH + (uint32_t)(mr0 + rA) * 128;
        uint32_t aAL = st + OFF_AL + (uint32_t)(mr0 + rA) * 128;
        uint32_t aBH = st + OFF_BH + (uint32_t)(nc0 + rB) * 128;
        uint32_t aBL = st + OFF_BL + (uint32_t)(nc0 + rB) * 128;

        #pragma unroll
        for (int ks = 0; ks < 4; ks++) {
            uint32_t gA = (uint32_t)(((ks * 2 + kgA) ^ swA) << 4);
            uint32_t gB = (uint32_t)(((ks * 2 + kgB) ^ swB) << 4);
            uint32_t ah[2][4], al[2][4], bh[8], bl[8];
            ldm4(ah[0], aAH + gA);
            ldm4(ah[1], aAH + 2048 + gA);       // +16 rows
            ldm4(al[0], aAL + gA);
            ldm4(al[1], aAL + 2048 + gA);
            ldm4(bh + 0, aBH + gB);             // n-tiles 0,1
            ldm4(bh + 4, aBH + 2048 + gB);      // n-tiles 2,3
            ldm4(bl + 0, aBL + gB);
            ldm4(bl + 4, aBL + 2048 + gB);
            #pragma unroll
            for (int mi = 0; mi < 2; mi++)
                #pragma unroll
                for (int ni = 0; ni < 4; ni++) {
                    mma16816(c[mi][ni], ah[mi], bh + ni * 2);
                    mma16816(c[mi][ni], ah[mi], bl + ni * 2);
                    mma16816(c[mi][ni], al[mi], bh + ni * 2);
                }
        }

        if (kc + 1 < NKC) {
            uint32_t st2 = base + (uint32_t)((kc + 1) & 1) * STAGE_B;
            #pragma unroll
            for (int p = 0; p < 2; p++) {
                uint32_t h0, l0, h1, l1, h2, l2, h3, l3;
                cvt2(fa[2*p].x, fa[2*p].y, h0, l0);
                cvt2(fa[2*p].z, fa[2*p].w, h1, l1);
                cvt2(fa[2*p+1].x, fa[2*p+1].y, h2, l2);
                cvt2(fa[2*p+1].z, fa[2*p+1].w, h3, l3);
                uint32_t sg = (uint32_t)(((g0 + p) ^ (arow & 7)) << 4);
                sts128(st2 + OFF_AH + strow + sg, h0, h1, h2, h3);
                sts128(st2 + OFF_AL + strow + sg, l0, l1, l2, l3);
                cvt2(fb[2*p].x, fb[2*p].y, h0, l0);
                cvt2(fb[2*p].z, fb[2*p].w, h1, l1);
                cvt2(fb[2*p+1].x, fb[2*p+1].y, h2, l2);
                cvt2(fb[2*p+1].z, fb[2*p+1].w, h3, l3);
                sts128(st2 + OFF_BH + strow + sg, h0, h1, h2, h3);
                sts128(st2 + OFF_BL + strow + sg, l0, l1, l2, l3);
            }
            __syncthreads();
        }
    }

    // ---- fused epilogue ----
    if (tid < 128) wpart[tid] = 0.f;
    __syncthreads();

    // per-thread u columns: u = u0 + nc0 + ni*8 + 2*(lane&3) + {0,1}
    float vv[4][2], pqv[4][2];
    {
        const float* pqp = g_pq + (size_t)n * U_D + u0 + nc0;
        const float* vp  = v + u0 + nc0;
        #pragma unroll
        for (int ni = 0; ni < 4; ni++) {
            int cb = ni * 8 + 2 * (lane & 3);
            vv[ni][0] = vp[cb];     vv[ni][1] = vp[cb + 1];
            pqv[ni][0] = pqp[cb];   pqv[ni][1] = pqp[cb + 1];
        }
    }
    #pragma unroll
    for (int mi = 0; mi < 2; mi++) {
        float s1 = 0.f, s2 = 0.f;
        #pragma unroll
        for (int ni = 0; ni < 4; ni++) {
            s1 += vv[ni][0] * tanhf(c[mi][ni][0] + pqv[ni][0]);
            s1 += vv[ni][1] * tanhf(c[mi][ni][1] + pqv[ni][1]);
            s2 += vv[ni][0] * tanhf(c[mi][ni][2] + pqv[ni][0]);
            s2 += vv[ni][1] * tanhf(c[mi][ni][3] + pqv[ni][1]);
        }
        s1 += __shfl_xor_sync(0xffffffffu, s1, 1);
        s1 += __shfl_xor_sync(0xffffffffu, s1, 2);
        s2 += __shfl_xor_sync(0xffffffffu, s2, 1);
        s2 += __shfl_xor_sync(0xffffffffu, s2, 2);
        if ((lane & 3) == 0) {
            int r1 = mr0 + mi * 16 + (lane >> 2);
            atomicAdd(&wpart[r1], s1);
            atomicAdd(&wpart[r1 + 8], s2);
        }
    }
    __syncthreads();
    if (tid < 128 && (t0 + tid) < len)
        atomicAdd(&g_weights[n * T_S + t0 + tid], wpart[tid]);
}

// ===========================================================================
extern "C" void kernel_launch(void* const* d_in, const int* in_sizes, int n_in,
                              void* d_out, int out_size) {
    const float* q       = (const float*)d_in[0];  // [32,1,1024]
    const float* enc     = (const float*)d_in[1];  // [32,2048,1024]
    const int*   lengths = (const int*)  d_in[2];  // [32]
    const float* v       = (const float*)d_in[3];  // [1024]
    const float* Wq      = (const float*)d_in[4];  // [1024,1024]
    const float* Wk      = (const float*)d_in[5];  // [1024,1024]

    float* out   = (float*)d_out;
    float* ctx   = out;                 // contexts   [32,1024]
    float* align = out + N_B * D_E;     // alignments [32,2048]

    cudaFuncSetAttribute(weights_tc_kernel,
                         cudaFuncAttributeMaxDynamicSharedMemorySize, DYN_SMEM);

    zero_weights_kernel<<<(N_B * T_S + 255) / 256, 256>>>();
    pq_kernel<<<(N_B * U_D) / 8, 256>>>(q, Wq);

    dim3 g(U_D / 128, T_S / 128, N_B);   // u fastest for L2 reuse of enc tiles
    weights_tc_kernel<<<g, 512, DYN_SMEM>>>(enc, Wk, v, lengths);

    softmax_kernel<<<N_B, 256>>>(lengths, align);

    dim3 gc(D_E / 256, N_B);
    context_kernel<<<gc, 256>>>(enc, lengths, align, ctx);
}

// round 6
// speedup vs baseline: 1.9794x; 1.0167x over previous
#include <cuda_runtime.h>
#include <cuda_fp16.h>
#include <cstdint>

#define N_B 32
#define T_S 2048
#define D_E 1024
#define U_D 1024

// Scratch (device globals: no allocation allowed)
__device__ float g_pq[N_B * U_D];          // proj_query [32,1024]
__device__ float g_weights[N_B * T_S];     // logits     [32,2048]
__device__ __half g_encH[N_B * T_S * D_E]; // enc hi fp16 (128MB)
__device__ __half g_encL[N_B * T_S * D_E]; // enc lo fp16 (128MB)
__device__ __half g_wkH[U_D * D_E];        // Wk hi fp16 (2MB)
__device__ __half g_wkL[U_D * D_E];        // Wk lo fp16 (2MB)

// ===========================================================================
// Helpers
// ===========================================================================
__device__ __forceinline__ uint32_t smem_u32(const void* p) {
    uint32_t a;
    asm("{ .reg .u64 t; cvta.to.shared.u64 t, %1; cvt.u32.u64 %0, t; }"
        : "=r"(a) : "l"(p));
    return a;
}
__device__ __forceinline__ void ldm4(uint32_t* r, uint32_t addr) {
    asm volatile("ldmatrix.sync.aligned.m8n8.x4.shared.b16 {%0,%1,%2,%3}, [%4];"
                 : "=r"(r[0]), "=r"(r[1]), "=r"(r[2]), "=r"(r[3]) : "r"(addr));
}
__device__ __forceinline__ void mma16816(float* c, const uint32_t* a,
                                         const uint32_t* b) {
    asm volatile(
        "mma.sync.aligned.m16n8k16.row.col.f32.f16.f16.f32 "
        "{%0,%1,%2,%3}, {%4,%5,%6,%7}, {%8,%9}, {%0,%1,%2,%3};"
        : "+f"(c[0]), "+f"(c[1]), "+f"(c[2]), "+f"(c[3])
        : "r"(a[0]), "r"(a[1]), "r"(a[2]), "r"(a[3]), "r"(b[0]), "r"(b[1]));
}
__device__ __forceinline__ void cpasync16(uint32_t dst, const void* src) {
    asm volatile("cp.async.cg.shared.global [%0], [%1], 16;"
                 :: "r"(dst), "l"(src) : "memory");
}
__device__ __forceinline__ void cp_commit() {
    asm volatile("cp.async.commit_group;" ::: "memory");
}

// ===========================================================================
// Precompute: fp32 -> (hi fp16, lo fp16)
// ===========================================================================
__device__ __forceinline__ void split8(const float4 f0, const float4 f1,
                                       uint4& hi, uint4& lo) {
    __half2 h0 = __floats2half2_rn(f0.x, f0.y);
    __half2 h1 = __floats2half2_rn(f0.z, f0.w);
    __half2 h2 = __floats2half2_rn(f1.x, f1.y);
    __half2 h3 = __floats2half2_rn(f1.z, f1.w);
    float2 a0 = __half22float2(h0), a1 = __half22float2(h1);
    float2 a2 = __half22float2(h2), a3 = __half22float2(h3);
    __half2 l0 = __floats2half2_rn(f0.x - a0.x, f0.y - a0.y);
    __half2 l1 = __floats2half2_rn(f0.z - a1.x, f0.w - a1.y);
    __half2 l2 = __floats2half2_rn(f1.x - a2.x, f1.y - a2.y);
    __half2 l3 = __floats2half2_rn(f1.z - a3.x, f1.w - a3.y);
    hi = make_uint4(*(uint32_t*)&h0, *(uint32_t*)&h1, *(uint32_t*)&h2, *(uint32_t*)&h3);
    lo = make_uint4(*(uint32_t*)&l0, *(uint32_t*)&l1, *(uint32_t*)&l2, *(uint32_t*)&l3);
}

// enc: one block = 2 rows (2048 floats), 256 threads x 8 floats
__global__ void convert_enc_kernel(const float* __restrict__ enc,
                                   const int* __restrict__ lengths) {
    int n  = blockIdx.y;
    int t0 = blockIdx.x * 2;
    int lenc = (lengths[n] + 127) & ~127;   // only rows the GEMM will read
    if (t0 >= lenc) return;
    size_t base = ((size_t)n * T_S + t0) * D_E + (size_t)threadIdx.x * 8;
    float4 f0 = *(const float4*)(enc + base);
    float4 f1 = *(const float4*)(enc + base + 4);
    uint4 hi, lo;
    split8(f0, f1, hi, lo);
    *(uint4*)(g_encH + base) = hi;
    *(uint4*)(g_encL + base) = lo;
}

// Wk: 1M floats, 512 blocks x 256 threads x 8 floats
__global__ void convert_wk_kernel(const float* __restrict__ Wk) {
    size_t base = ((size_t)blockIdx.x * 256 + threadIdx.x) * 8;
    float4 f0 = *(const float4*)(Wk + base);
    float4 f1 = *(const float4*)(Wk + base + 4);
    uint4 hi, lo;
    split8(f0, f1, hi, lo);
    *(uint4*)(g_wkH + base) = hi;
    *(uint4*)(g_wkL + base) = lo;
}

// ===========================================================================
// Simple kernels
// ===========================================================================
__global__ void zero_weights_kernel() {
    int i = blockIdx.x * blockDim.x + threadIdx.x;
    if (i < N_B * T_S) g_weights[i] = 0.f;
}

__global__ void pq_kernel(const float* __restrict__ q, const float* __restrict__ Wq) {
    int wid  = (blockIdx.x * blockDim.x + threadIdx.x) >> 5;
    int lane = threadIdx.x & 31;
    if (wid >= N_B * U_D) return;
    int n = wid >> 10;
    int u = wid & 1023;
    const float4* q4 = (const float4*)(q + (size_t)n * D_E);
    const float4* w4 = (const float4*)(Wq + (size_t)u * D_E);
    float s = 0.f;
    for (int i = lane; i < D_E / 4; i += 32) {
        float4 a = q4[i], b = w4[i];
        s += a.x * b.x + a.y * b.y + a.z * b.z + a.w * b.w;
    }
    #pragma unroll
    for (int o = 16; o > 0; o >>= 1) s += __shfl_down_sync(0xffffffffu, s, o);
    if (lane == 0) g_pq[wid] = s;
}

__global__ void softmax_kernel(const int* __restrict__ lengths,
                               float* __restrict__ align) {
    int n   = blockIdx.x;
    int len = lengths[n];
    int tid = threadIdx.x;
    const float* w = g_weights + n * T_S;
    __shared__ float sm[256];

    float m = -1e30f;
    for (int t = tid; t < len; t += 256) m = fmaxf(m, w[t]);
    sm[tid] = m; __syncthreads();
    for (int s = 128; s > 0; s >>= 1) {
        if (tid < s) sm[tid] = fmaxf(sm[tid], sm[tid + s]);
        __syncthreads();
    }
    m = sm[0]; __syncthreads();

    float sum = 0.f;
    for (int t = tid; t < len; t += 256) sum += expf(w[t] - m);
    sm[tid] = sum; __syncthreads();
    for (int s = 128; s > 0; s >>= 1) {
        if (tid < s) sm[tid] += sm[tid + s];
        __syncthreads();
    }
    float inv = 1.f / sm[0];

    for (int t = tid; t < T_S; t += 256)
        align[(size_t)n * T_S + t] = (t < len) ? expf(w[t] - m) * inv : 0.f;
}

__global__ void context_kernel(const float* __restrict__ enc,
                               const int* __restrict__ lengths,
                               const float* __restrict__ align,
                               float* __restrict__ ctx) {
    int n   = blockIdx.y;
    int e   = blockIdx.x * 256 + threadIdx.x;
    int len = lengths[n];
    const float* al = align + (size_t)n * T_S;
    const float* E  = enc + (size_t)n * T_S * D_E + e;
    float c0 = 0.f, c1 = 0.f, c2 = 0.f, c3 = 0.f;
    int t = 0;
    for (; t + 4 <= len; t += 4) {
        c0 += al[t + 0] * E[(size_t)(t + 0) * D_E];
        c1 += al[t + 1] * E[(size_t)(t + 1) * D_E];
        c2 += al[t + 2] * E[(size_t)(t + 2) * D_E];
        c3 += al[t + 3] * E[(size_t)(t + 3) * D_E];
    }
    for (; t < len; t++) c0 += al[t] * E[(size_t)t * D_E];
    ctx[(size_t)n * D_E + e] = (c0 + c1) + (c2 + c3);
}

// ===========================================================================
// mma.sync 3xFP16-split fused logits GEMM (cp.async from precomputed halves)
//   C[128(t) x 128(u)] = enc_tile @ Wk_tile^T  (K=1024)
//   logits[n,t] += sum_u v[u]*tanh(C + pq[n,u])
// ===========================================================================
#define BKF     64                    // fp32 K elems per chunk
#define NKC     (D_E / BKF)           // 16 chunks
#define OFF_AH  0
#define OFF_AL  16384
#define OFF_BH  32768
#define OFF_BL  49152
#define STAGE_B 65536
#define NST     3
#define DYN_SMEM (NST * STAGE_B)

__global__ void __launch_bounds__(512, 1)
weights_tc_kernel(const float* __restrict__ v, const int* __restrict__ lengths) {
    int n  = blockIdx.z;
    int t0 = blockIdx.y * 128;
    int u0 = blockIdx.x * 128;
    int len = lengths[n];
    if (t0 >= len) return;

    extern __shared__ char dyn_smem[];
    __shared__ float wpart[128];
    uint32_t base = smem_u32(dyn_smem);

    int tid  = threadIdx.x;
    int wid  = tid >> 5;
    int lane = tid & 31;
    int mr0 = (wid >> 2) * 32;
    int nc0 = (wid & 3) * 32;

    // ldmatrix per-thread geometry
    int rA  = lane & 15;
    int kgA = lane >> 4;
    int swA = rA & 7;
    int rB  = (lane & 7) | ((lane >> 4) << 3);
    int kgB = (lane >> 3) & 1;
    int swB = rB & 7;

    // cp.async geometry: row = tid>>2, two 16B groups per tile per thread
    int arow = tid >> 2;
    int g0   = (tid & 3) * 2;
    const __half* srcAH = g_encH + ((size_t)n * T_S + t0 + arow) * D_E + g0 * 8;
    const __half* srcAL = g_encL + ((size_t)n * T_S + t0 + arow) * D_E + g0 * 8;
    const __half* srcBH = g_wkH + ((size_t)(u0 + arow)) * D_E + g0 * 8;
    const __half* srcBL = g_wkL + ((size_t)(u0 + arow)) * D_E + g0 * 8;
    uint32_t d0 = base + (uint32_t)arow * 128 + (uint32_t)((g0 ^ (arow & 7)) << 4);
    uint32_t d1 = base + (uint32_t)arow * 128 + (uint32_t)(((g0 + 1) ^ (arow & 7)) << 4);

    float c[2][4][4];
    #pragma unroll
    for (int mi = 0; mi < 2; mi++)
        #pragma unroll
        for (int ni = 0; ni < 4; ni++)
            #pragma unroll
            for (int k = 0; k < 4; k++) c[mi][ni][k] = 0.f;

    // ---- issue prologue stages 0..NST-2 ----
    #pragma unroll
    for (int s = 0; s < NST - 1; s++) {
        uint32_t st = (uint32_t)s * STAGE_B;
        size_t ko = (size_t)s * BKF;
        cpasync16(d0 + st + OFF_AH, srcAH + ko);
        cpasync16(d1 + st + OFF_AH, srcAH + ko + 8);
        cpasync16(d0 + st + OFF_AL, srcAL + ko);
        cpasync16(d1 + st + OFF_AL, srcAL + ko + 8);
        cpasync16(d0 + st + OFF_BH, srcBH + ko);
        cpasync16(d1 + st + OFF_BH, srcBH + ko + 8);
        cpasync16(d0 + st + OFF_BL, srcBL + ko);
        cpasync16(d1 + st + OFF_BL, srcBL + ko + 8);
        cp_commit();
    }

    for (int kc = 0; kc < NKC; kc++) {
        if (kc + 1 < NKC)
            asm volatile("cp.async.wait_group 1;" ::: "memory");
        else
            asm volatile("cp.async.wait_group 0;" ::: "memory");
        __syncthreads();

        // prefetch stage kc+NST-1 (safe: all warps are past chunk kc-1)
        if (kc + NST - 1 < NKC) {
            uint32_t st = (uint32_t)((kc + NST - 1) % NST) * STAGE_B;
            size_t ko = (size_t)(kc + NST - 1) * BKF;
            cpasync16(d0 + st + OFF_AH, srcAH + ko);
            cpasync16(d1 + st + OFF_AH, srcAH + ko + 8);
            cpasync16(d0 + st + OFF_AL, srcAL + ko);
            cpasync16(d1 + st + OFF_AL, srcAL + ko + 8);
            cpasync16(d0 + st + OFF_BH, srcBH + ko);
            cpasync16(d1 + st + OFF_BH, srcBH + ko + 8);
            cpasync16(d0 + st + OFF_BL, srcBL + ko);
            cpasync16(d1 + st + OFF_BL, srcBL + ko + 8);
            cp_commit();
        }

        // ---- compute chunk kc ----
        uint32_t st  = base + (uint32_t)(kc % NST) * STAGE_B;
        uint32_t aAH = st + OFF_AH + (uint32_t)(mr0 + rA) * 128;
        uint32_t aAL = st + OFF_AL + (uint32_t)(mr0 + rA) * 128;
        uint32_t aBH = st + OFF_BH + (uint32_t)(nc0 + rB) * 128;
        uint32_t aBL = st + OFF_BL + (uint32_t)(nc0 + rB) * 128;

        #pragma unroll
        for (int ks = 0; ks < 4; ks++) {
            uint32_t gA = (uint32_t)(((ks * 2 + kgA) ^ swA) << 4);
            uint32_t gB = (uint32_t)(((ks * 2 + kgB) ^ swB) << 4);
            uint32_t ah[2][4], al[2][4], bh[8], bl[8];
            ldm4(ah[0], aAH + gA);
            ldm4(ah[1], aAH + 2048 + gA);
            ldm4(al[0], aAL + gA);
            ldm4(al[1], aAL + 2048 + gA);
            ldm4(bh + 0, aBH + gB);
            ldm4(bh + 4, aBH + 2048 + gB);
            ldm4(bl + 0, aBL + gB);
            ldm4(bl + 4, aBL + 2048 + gB);
            #pragma unroll
            for (int mi = 0; mi < 2; mi++)
                #pragma unroll
                for (int ni = 0; ni < 4; ni++) {
                    mma16816(c[mi][ni], ah[mi], bh + ni * 2);
                    mma16816(c[mi][ni], ah[mi], bl + ni * 2);
                    mma16816(c[mi][ni], al[mi], bh + ni * 2);
                }
        }
    }

    // ---- fused epilogue ----
    if (tid < 128) wpart[tid] = 0.f;
    __syncthreads();

    float vv[4][2], pqv[4][2];
    {
        const float* pqp = g_pq + (size_t)n * U_D + u0 + nc0;
        const float* vp  = v + u0 + nc0;
        #pragma unroll
        for (int ni = 0; ni < 4; ni++) {
            int cb = ni * 8 + 2 * (lane & 3);
            vv[ni][0] = vp[cb];     vv[ni][1] = vp[cb + 1];
            pqv[ni][0] = pqp[cb];   pqv[ni][1] = pqp[cb + 1];
        }
    }
    #pragma unroll
    for (int mi = 0; mi < 2; mi++) {
        float s1 = 0.f, s2 = 0.f;
        #pragma unroll
        for (int ni = 0; ni < 4; ni++) {
            s1 += vv[ni][0] * tanhf(c[mi][ni][0] + pqv[ni][0]);
            s1 += vv[ni][1] * tanhf(c[mi][ni][1] + pqv[ni][1]);
            s2 += vv[ni][0] * tanhf(c[mi][ni][2] + pqv[ni][0]);
            s2 += vv[ni][1] * tanhf(c[mi][ni][3] + pqv[ni][1]);
        }
        s1 += __shfl_xor_sync(0xffffffffu, s1, 1);
        s1 += __shfl_xor_sync(0xffffffffu, s1, 2);
        s2 += __shfl_xor_sync(0xffffffffu, s2, 1);
        s2 += __shfl_xor_sync(0xffffffffu, s2, 2);
        if ((lane & 3) == 0) {
            int r1 = mr0 + mi * 16 + (lane >> 2);
            atomicAdd(&wpart[r1], s1);
            atomicAdd(&wpart[r1 + 8], s2);
        }
    }
    __syncthreads();
    if (tid < 128 && (t0 + tid) < len)
        atomicAdd(&g_weights[n * T_S + t0 + tid], wpart[tid]);
}

// ===========================================================================
extern "C" void kernel_launch(void* const* d_in, const int* in_sizes, int n_in,
                              void* d_out, int out_size) {
    const float* q       = (const float*)d_in[0];  // [32,1,1024]
    const float* enc     = (const float*)d_in[1];  // [32,2048,1024]
    const int*   lengths = (const int*)  d_in[2];  // [32]
    const float* v       = (const float*)d_in[3];  // [1024]
    const float* Wq      = (const float*)d_in[4];  // [1024,1024]
    const float* Wk      = (const float*)d_in[5];  // [1024,1024]

    float* out   = (float*)d_out;
    float* ctx   = out;                 // contexts   [32,1024]
    float* align = out + N_B * D_E;     // alignments [32,2048]

    cudaFuncSetAttribute(weights_tc_kernel,
                         cudaFuncAttributeMaxDynamicSharedMemorySize, DYN_SMEM);

    zero_weights_kernel<<<(N_B * T_S + 255) / 256, 256>>>();
    convert_wk_kernel<<<512, 256>>>(Wk);
    convert_enc_kernel<<<dim3(T_S / 2, N_B), 256>>>(enc, lengths);
    pq_kernel<<<(N_B * U_D) / 8, 256>>>(q, Wq);

    dim3 g(U_D / 128, T_S / 128, N_B);   // u fastest for L2 reuse of enc tiles
    weights_tc_kernel<<<g, 512, DYN_SMEM>>>(v, lengths);

    softmax_kernel<<<N_B, 256>>>(lengths, align);

    dim3 gc(D_E / 256, N_B);
    context_kernel<<<gc, 256>>>(enc, lengths, align, ctx);
}

// round 7
// speedup vs baseline: 2.1322x; 1.0772x over previous
#include <cuda_runtime.h>
#include <cuda_fp16.h>
#include <cstdint>

#define N_B 32
#define T_S 2048
#define D_E 1024
#define U_D 1024

// Scratch (device globals: no allocation allowed)
__device__ float g_pq[N_B * U_D];          // proj_query [32,1024]
__device__ float g_weights[N_B * T_S];     // logits     [32,2048]
__device__ __half g_encH[N_B * T_S * D_E]; // enc hi fp16 (128MB)
__device__ __half g_encL[N_B * T_S * D_E]; // enc lo fp16 (128MB)
__device__ __half g_wkH[U_D * D_E];        // Wk hi fp16 (2MB)
__device__ __half g_wkL[U_D * D_E];        // Wk lo fp16 (2MB)

// ===========================================================================
// Helpers
// ===========================================================================
__device__ __forceinline__ uint32_t smem_u32(const void* p) {
    uint32_t a;
    asm("{ .reg .u64 t; cvta.to.shared.u64 t, %1; cvt.u32.u64 %0, t; }"
        : "=r"(a) : "l"(p));
    return a;
}
__device__ __forceinline__ void ldm4(uint32_t* r, uint32_t addr) {
    asm volatile("ldmatrix.sync.aligned.m8n8.x4.shared.b16 {%0,%1,%2,%3}, [%4];"
                 : "=r"(r[0]), "=r"(r[1]), "=r"(r[2]), "=r"(r[3]) : "r"(addr));
}
__device__ __forceinline__ void mma16816(float* c, const uint32_t* a,
                                         const uint32_t* b) {
    asm volatile(
        "mma.sync.aligned.m16n8k16.row.col.f32.f16.f16.f32 "
        "{%0,%1,%2,%3}, {%4,%5,%6,%7}, {%8,%9}, {%0,%1,%2,%3};"
        : "+f"(c[0]), "+f"(c[1]), "+f"(c[2]), "+f"(c[3])
        : "r"(a[0]), "r"(a[1]), "r"(a[2]), "r"(a[3]), "r"(b[0]), "r"(b[1]));
}
__device__ __forceinline__ void cpasync16(uint32_t dst, const void* src) {
    asm volatile("cp.async.cg.shared.global [%0], [%1], 16;"
                 :: "r"(dst), "l"(src) : "memory");
}
__device__ __forceinline__ void cp_commit() {
    asm volatile("cp.async.commit_group;" ::: "memory");
}

// ===========================================================================
// Precompute: fp32 -> (hi fp16, lo fp16)
// ===========================================================================
__device__ __forceinline__ void split8(const float4 f0, const float4 f1,
                                       uint4& hi, uint4& lo) {
    __half2 h0 = __floats2half2_rn(f0.x, f0.y);
    __half2 h1 = __floats2half2_rn(f0.z, f0.w);
    __half2 h2 = __floats2half2_rn(f1.x, f1.y);
    __half2 h3 = __floats2half2_rn(f1.z, f1.w);
    float2 a0 = __half22float2(h0), a1 = __half22float2(h1);
    float2 a2 = __half22float2(h2), a3 = __half22float2(h3);
    __half2 l0 = __floats2half2_rn(f0.x - a0.x, f0.y - a0.y);
    __half2 l1 = __floats2half2_rn(f0.z - a1.x, f0.w - a1.y);
    __half2 l2 = __floats2half2_rn(f1.x - a2.x, f1.y - a2.y);
    __half2 l3 = __floats2half2_rn(f1.z - a3.x, f1.w - a3.y);
    hi = make_uint4(*(uint32_t*)&h0, *(uint32_t*)&h1, *(uint32_t*)&h2, *(uint32_t*)&h3);
    lo = make_uint4(*(uint32_t*)&l0, *(uint32_t*)&l1, *(uint32_t*)&l2, *(uint32_t*)&l3);
}

__global__ void convert_enc_kernel(const float* __restrict__ enc,
                                   const int* __restrict__ lengths) {
    int n  = blockIdx.y;
    int t0 = blockIdx.x * 2;
    int lenc = (lengths[n] + 127) & ~127;
    if (t0 >= lenc) return;
    size_t base = ((size_t)n * T_S + t0) * D_E + (size_t)threadIdx.x * 8;
    float4 f0 = *(const float4*)(enc + base);
    float4 f1 = *(const float4*)(enc + base + 4);
    uint4 hi, lo;
    split8(f0, f1, hi, lo);
    *(uint4*)(g_encH + base) = hi;
    *(uint4*)(g_encL + base) = lo;
}

__global__ void convert_wk_kernel(const float* __restrict__ Wk) {
    size_t base = ((size_t)blockIdx.x * 256 + threadIdx.x) * 8;
    float4 f0 = *(const float4*)(Wk + base);
    float4 f1 = *(const float4*)(Wk + base + 4);
    uint4 hi, lo;
    split8(f0, f1, hi, lo);
    *(uint4*)(g_wkH + base) = hi;
    *(uint4*)(g_wkL + base) = lo;
}

// ===========================================================================
// Simple kernels
// ===========================================================================
__global__ void zero_weights_kernel() {
    int i = blockIdx.x * blockDim.x + threadIdx.x;
    if (i < N_B * T_S) g_weights[i] = 0.f;
}

__global__ void pq_kernel(const float* __restrict__ q, const float* __restrict__ Wq) {
    int wid  = (blockIdx.x * blockDim.x + threadIdx.x) >> 5;
    int lane = threadIdx.x & 31;
    if (wid >= N_B * U_D) return;
    int n = wid >> 10;
    int u = wid & 1023;
    const float4* q4 = (const float4*)(q + (size_t)n * D_E);
    const float4* w4 = (const float4*)(Wq + (size_t)u * D_E);
    float s = 0.f;
    for (int i = lane; i < D_E / 4; i += 32) {
        float4 a = q4[i], b = w4[i];
        s += a.x * b.x + a.y * b.y + a.z * b.z + a.w * b.w;
    }
    #pragma unroll
    for (int o = 16; o > 0; o >>= 1) s += __shfl_down_sync(0xffffffffu, s, o);
    if (lane == 0) g_pq[wid] = s;
}

__global__ void softmax_kernel(const int* __restrict__ lengths,
                               float* __restrict__ align) {
    int n   = blockIdx.x;
    int len = lengths[n];
    int tid = threadIdx.x;
    const float* w = g_weights + n * T_S;
    __shared__ float sm[256];

    float m = -1e30f;
    for (int t = tid; t < len; t += 256) m = fmaxf(m, w[t]);
    sm[tid] = m; __syncthreads();
    for (int s = 128; s > 0; s >>= 1) {
        if (tid < s) sm[tid] = fmaxf(sm[tid], sm[tid + s]);
        __syncthreads();
    }
    m = sm[0]; __syncthreads();

    float sum = 0.f;
    for (int t = tid; t < len; t += 256) sum += expf(w[t] - m);
    sm[tid] = sum; __syncthreads();
    for (int s = 128; s > 0; s >>= 1) {
        if (tid < s) sm[tid] += sm[tid + s];
        __syncthreads();
    }
    float inv = 1.f / sm[0];

    for (int t = tid; t < T_S; t += 256)
        align[(size_t)n * T_S + t] = (t < len) ? expf(w[t] - m) * inv : 0.f;
}

__global__ void context_kernel(const float* __restrict__ enc,
                               const int* __restrict__ lengths,
                               const float* __restrict__ align,
                               float* __restrict__ ctx) {
    int n   = blockIdx.y;
    int e   = blockIdx.x * 256 + threadIdx.x;
    int len = lengths[n];
    const float* al = align + (size_t)n * T_S;
    const float* E  = enc + (size_t)n * T_S * D_E + e;
    float c0 = 0.f, c1 = 0.f, c2 = 0.f, c3 = 0.f;
    int t = 0;
    for (; t + 4 <= len; t += 4) {
        c0 += al[t + 0] * E[(size_t)(t + 0) * D_E];
        c1 += al[t + 1] * E[(size_t)(t + 1) * D_E];
        c2 += al[t + 2] * E[(size_t)(t + 2) * D_E];
        c3 += al[t + 3] * E[(size_t)(t + 3) * D_E];
    }
    for (; t < len; t++) c0 += al[t] * E[(size_t)t * D_E];
    ctx[(size_t)n * D_E + e] = (c0 + c1) + (c2 + c3);
}

// ===========================================================================
// mma.sync 3xFP16-split fused logits GEMM — fragment-double-buffered mainloop
// ===========================================================================
#define BKF     64                    // fp32 K elems per chunk
#define NKC     (D_E / BKF)           // 16 chunks
#define OFF_AH  0
#define OFF_AL  16384
#define OFF_BH  32768
#define OFF_BL  49152
#define STAGE_B 65536
#define NST     3
#define DYN_SMEM (NST * STAGE_B)

__global__ void __launch_bounds__(512, 1)
weights_tc_kernel(const float* __restrict__ v, const int* __restrict__ lengths) {
    int n  = blockIdx.z;
    int t0 = blockIdx.y * 128;
    int u0 = blockIdx.x * 128;
    int len = lengths[n];
    if (t0 >= len) return;

    extern __shared__ char dyn_smem[];
    __shared__ float wpart[128];
    uint32_t base = smem_u32(dyn_smem);

    int tid  = threadIdx.x;
    int wid  = tid >> 5;
    int lane = tid & 31;
    int mr0 = (wid >> 2) * 32;
    int nc0 = (wid & 3) * 32;

    // ldmatrix per-thread geometry
    int rA  = lane & 15;
    int kgA = lane >> 4;
    int swA = rA & 7;
    int rB  = (lane & 7) | ((lane >> 4) << 3);
    int kgB = (lane >> 3) & 1;
    int swB = rB & 7;
    uint32_t rowA = (uint32_t)(mr0 + rA) * 128;   // byte offset within tile
    uint32_t rowB = (uint32_t)(nc0 + rB) * 128;

    // cp.async geometry
    int arow = tid >> 2;
    int g0   = (tid & 3) * 2;
    const __half* srcAH = g_encH + ((size_t)n * T_S + t0 + arow) * D_E + g0 * 8;
    const __half* srcAL = g_encL + ((size_t)n * T_S + t0 + arow) * D_E + g0 * 8;
    const __half* srcBH = g_wkH + ((size_t)(u0 + arow)) * D_E + g0 * 8;
    const __half* srcBL = g_wkL + ((size_t)(u0 + arow)) * D_E + g0 * 8;
    uint32_t d0 = base + (uint32_t)arow * 128 + (uint32_t)((g0 ^ (arow & 7)) << 4);
    uint32_t d1 = base + (uint32_t)arow * 128 + (uint32_t)(((g0 + 1) ^ (arow & 7)) << 4);

    float c[2][4][4];
    #pragma unroll
    for (int mi = 0; mi < 2; mi++)
        #pragma unroll
        for (int ni = 0; ni < 4; ni++)
            #pragma unroll
            for (int k = 0; k < 4; k++) c[mi][ni][k] = 0.f;

    // Double-buffered fragments
    uint32_t ah[2][2][4], al[2][2][4], bh[2][8], bl[2][8];

#define CP_STAGE(stg, kchunk) do {                                           \
        uint32_t _st = (uint32_t)(stg) * STAGE_B;                            \
        size_t _ko = (size_t)(kchunk) * BKF;                                 \
        cpasync16(d0 + _st + OFF_AH, srcAH + _ko);                           \
        cpasync16(d1 + _st + OFF_AH, srcAH + _ko + 8);                       \
        cpasync16(d0 + _st + OFF_AL, srcAL + _ko);                           \
        cpasync16(d1 + _st + OFF_AL, srcAL + _ko + 8);                       \
        cpasync16(d0 + _st + OFF_BH, srcBH + _ko);                           \
        cpasync16(d1 + _st + OFF_BH, srcBH + _ko + 8);                       \
        cpasync16(d0 + _st + OFF_BL, srcBL + _ko);                           \
        cpasync16(d1 + _st + OFF_BL, srcBL + _ko + 8);                       \
        cp_commit();                                                         \
    } while (0)

#define LOAD_FRAGS(buf, stg, ks) do {                                        \
        uint32_t _sb = base + (uint32_t)(stg) * STAGE_B;                     \
        uint32_t _gA = (uint32_t)((((ks) * 2 + kgA) ^ swA) << 4);            \
        uint32_t _gB = (uint32_t)((((ks) * 2 + kgB) ^ swB) << 4);            \
        uint32_t _aAH = _sb + OFF_AH + rowA;                                 \
        uint32_t _aAL = _sb + OFF_AL + rowA;                                 \
        uint32_t _aBH = _sb + OFF_BH + rowB;                                 \
        uint32_t _aBL = _sb + OFF_BL + rowB;                                 \
        ldm4(ah[buf][0], _aAH + _gA);                                        \
        ldm4(ah[buf][1], _aAH + 2048 + _gA);                                 \
        ldm4(al[buf][0], _aAL + _gA);                                        \
        ldm4(al[buf][1], _aAL + 2048 + _gA);                                 \
        ldm4(bh[buf] + 0, _aBH + _gB);                                       \
        ldm4(bh[buf] + 4, _aBH + 2048 + _gB);                                \
        ldm4(bl[buf] + 0, _aBL + _gB);                                       \
        ldm4(bl[buf] + 4, _aBL + 2048 + _gB);                                \
    } while (0)

#define MMA_STEP(buf) do {                                                   \
        _Pragma("unroll")                                                    \
        for (int mi = 0; mi < 2; mi++)                                       \
            _Pragma("unroll")                                                \
            for (int ni = 0; ni < 4; ni++) {                                 \
                mma16816(c[mi][ni], ah[buf][mi], bh[buf] + ni * 2);          \
                mma16816(c[mi][ni], ah[buf][mi], bl[buf] + ni * 2);          \
                mma16816(c[mi][ni], al[buf][mi], bh[buf] + ni * 2);          \
            }                                                                \
    } while (0)

    // ---- prologue: stages 0 and 1 in flight ----
    CP_STAGE(0, 0);
    CP_STAGE(1, 1);

    for (int kc = 0; kc < NKC; kc++) {
        asm volatile("cp.async.wait_group 0;" ::: "memory");
        __syncthreads();
        if (kc + 2 < NKC)
            CP_STAGE((kc + 2) % NST, kc + 2);

        int stg = kc % NST;
        if (kc == 0)
            LOAD_FRAGS(0, 0, 0);

        // ks=0
        LOAD_FRAGS(1, stg, 1);
        MMA_STEP(0);
        // ks=1
        LOAD_FRAGS(0, stg, 2);
        MMA_STEP(1);
        // ks=2
        LOAD_FRAGS(1, stg, 3);
        MMA_STEP(0);
        // ks=3 (prefetch next chunk's ks=0 across the barrier)
        if (kc + 1 < NKC)
            LOAD_FRAGS(0, (kc + 1) % NST, 0);
        MMA_STEP(1);
    }

    // ---- fused epilogue ----
    if (tid < 128) wpart[tid] = 0.f;
    __syncthreads();

    float vv[4][2], pqv[4][2];
    {
        const float* pqp = g_pq + (size_t)n * U_D + u0 + nc0;
        const float* vp  = v + u0 + nc0;
        #pragma unroll
        for (int ni = 0; ni < 4; ni++) {
            int cb = ni * 8 + 2 * (lane & 3);
            vv[ni][0] = vp[cb];     vv[ni][1] = vp[cb + 1];
            pqv[ni][0] = pqp[cb];   pqv[ni][1] = pqp[cb + 1];
        }
    }
    #pragma unroll
    for (int mi = 0; mi < 2; mi++) {
        float s1 = 0.f, s2 = 0.f;
        #pragma unroll
        for (int ni = 0; ni < 4; ni++) {
            s1 += vv[ni][0] * tanhf(c[mi][ni][0] + pqv[ni][0]);
            s1 += vv[ni][1] * tanhf(c[mi][ni][1] + pqv[ni][1]);
            s2 += vv[ni][0] * tanhf(c[mi][ni][2] + pqv[ni][0]);
            s2 += vv[ni][1] * tanhf(c[mi][ni][3] + pqv[ni][1]);
        }
        s1 += __shfl_xor_sync(0xffffffffu, s1, 1);
        s1 += __shfl_xor_sync(0xffffffffu, s1, 2);
        s2 += __shfl_xor_sync(0xffffffffu, s2, 1);
        s2 += __shfl_xor_sync(0xffffffffu, s2, 2);
        if ((lane & 3) == 0) {
            int r1 = mr0 + mi * 16 + (lane >> 2);
            atomicAdd(&wpart[r1], s1);
            atomicAdd(&wpart[r1 + 8], s2);
        }
    }
    __syncthreads();
    if (tid < 128 && (t0 + tid) < len)
        atomicAdd(&g_weights[n * T_S + t0 + tid], wpart[tid]);
}

// ===========================================================================
extern "C" void kernel_launch(void* const* d_in, const int* in_sizes, int n_in,
                              void* d_out, int out_size) {
    const float* q       = (const float*)d_in[0];  // [32,1,1024]
    const float* enc     = (const float*)d_in[1];  // [32,2048,1024]
    const int*   lengths = (const int*)  d_in[2];  // [32]
    const float* v       = (const float*)d_in[3];  // [1024]
    const float* Wq      = (const float*)d_in[4];  // [1024,1024]
    const float* Wk      = (const float*)d_in[5];  // [1024,1024]

    float* out   = (float*)d_out;
    float* ctx   = out;                 // contexts   [32,1024]
    float* align = out + N_B * D_E;     // alignments [32,2048]

    cudaFuncSetAttribute(weights_tc_kernel,
                         cudaFuncAttributeMaxDynamicSharedMemorySize, DYN_SMEM);

    zero_weights_kernel<<<(N_B * T_S + 255) / 256, 256>>>();
    convert_wk_kernel<<<512, 256>>>(Wk);
    convert_enc_kernel<<<dim3(T_S / 2, N_B), 256>>>(enc, lengths);
    pq_kernel<<<(N_B * U_D) / 8, 256>>>(q, Wq);

    dim3 g(U_D / 128, T_S / 128, N_B);   // u fastest for L2 reuse of enc tiles
    weights_tc_kernel<<<g, 512, DYN_SMEM>>>(v, lengths);

    softmax_kernel<<<N_B, 256>>>(lengths, align);

    dim3 gc(D_E / 256, N_B);
    context_kernel<<<gc, 256>>>(enc, lengths, align, ctx);
}

// round 8
// speedup vs baseline: 2.1672x; 1.0164x over previous
#include <cuda_runtime.h>
#include <cuda_fp16.h>
#include <cstdint>

#define N_B 32
#define T_S 2048
#define D_E 1024
#define U_D 1024

// Scratch (device globals: no allocation allowed)
__device__ float g_pq[N_B * U_D];          // proj_query [32,1024]
__device__ float g_weights[N_B * T_S];     // logits     [32,2048]
__device__ __half g_encH[N_B * T_S * D_E]; // enc hi fp16 (128MB)
__device__ __half g_encL[N_B * T_S * D_E]; // enc lo fp16 (128MB)
__device__ __half g_wkH[U_D * D_E];        // Wk hi fp16 (2MB)
__device__ __half g_wkL[U_D * D_E];        // Wk lo fp16 (2MB)

// ===========================================================================
// Helpers
// ===========================================================================
__device__ __forceinline__ uint32_t smem_u32(const void* p) {
    uint32_t a;
    asm("{ .reg .u64 t; cvta.to.shared.u64 t, %1; cvt.u32.u64 %0, t; }"
        : "=r"(a) : "l"(p));
    return a;
}
__device__ __forceinline__ void ldm4(uint32_t* r, uint32_t addr) {
    asm volatile("ldmatrix.sync.aligned.m8n8.x4.shared.b16 {%0,%1,%2,%3}, [%4];"
                 : "=r"(r[0]), "=r"(r[1]), "=r"(r[2]), "=r"(r[3]) : "r"(addr));
}
__device__ __forceinline__ void mma16816(float* c, const uint32_t* a,
                                         const uint32_t* b) {
    asm volatile(
        "mma.sync.aligned.m16n8k16.row.col.f32.f16.f16.f32 "
        "{%0,%1,%2,%3}, {%4,%5,%6,%7}, {%8,%9}, {%0,%1,%2,%3};"
        : "+f"(c[0]), "+f"(c[1]), "+f"(c[2]), "+f"(c[3])
        : "r"(a[0]), "r"(a[1]), "r"(a[2]), "r"(a[3]), "r"(b[0]), "r"(b[1]));
}
__device__ __forceinline__ void cpasync16(uint32_t dst, const void* src) {
    asm volatile("cp.async.cg.shared.global [%0], [%1], 16;"
                 :: "r"(dst), "l"(src) : "memory");
}
__device__ __forceinline__ void cp_commit() {
    asm volatile("cp.async.commit_group;" ::: "memory");
}
__device__ __forceinline__ float tanh_fast(float x) {
    float y;
    asm("tanh.approx.f32 %0, %1;" : "=f"(y) : "f"(x));
    return y;
}

// ===========================================================================
// Precompute: fp32 -> (hi fp16, lo fp16)
// ===========================================================================
__device__ __forceinline__ void split8(const float4 f0, const float4 f1,
                                       uint4& hi, uint4& lo) {
    __half2 h0 = __floats2half2_rn(f0.x, f0.y);
    __half2 h1 = __floats2half2_rn(f0.z, f0.w);
    __half2 h2 = __floats2half2_rn(f1.x, f1.y);
    __half2 h3 = __floats2half2_rn(f1.z, f1.w);
    float2 a0 = __half22float2(h0), a1 = __half22float2(h1);
    float2 a2 = __half22float2(h2), a3 = __half22float2(h3);
    __half2 l0 = __floats2half2_rn(f0.x - a0.x, f0.y - a0.y);
    __half2 l1 = __floats2half2_rn(f0.z - a1.x, f0.w - a1.y);
    __half2 l2 = __floats2half2_rn(f1.x - a2.x, f1.y - a2.y);
    __half2 l3 = __floats2half2_rn(f1.z - a3.x, f1.w - a3.y);
    hi = make_uint4(*(uint32_t*)&h0, *(uint32_t*)&h1, *(uint32_t*)&h2, *(uint32_t*)&h3);
    lo = make_uint4(*(uint32_t*)&l0, *(uint32_t*)&l1, *(uint32_t*)&l2, *(uint32_t*)&l3);
}

__global__ void convert_enc_kernel(const float* __restrict__ enc,
                                   const int* __restrict__ lengths) {
    int n  = blockIdx.y;
    int t0 = blockIdx.x * 2;
    int lenc = (lengths[n] + 127) & ~127;
    if (t0 >= lenc) return;
    size_t base = ((size_t)n * T_S + t0) * D_E + (size_t)threadIdx.x * 8;
    float4 f0 = *(const float4*)(enc + base);
    float4 f1 = *(const float4*)(enc + base + 4);
    uint4 hi, lo;
    split8(f0, f1, hi, lo);
    *(uint4*)(g_encH + base) = hi;
    *(uint4*)(g_encL + base) = lo;
}

__global__ void convert_wk_kernel(const float* __restrict__ Wk) {
    size_t base = ((size_t)blockIdx.x * 256 + threadIdx.x) * 8;
    float4 f0 = *(const float4*)(Wk + base);
    float4 f1 = *(const float4*)(Wk + base + 4);
    uint4 hi, lo;
    split8(f0, f1, hi, lo);
    *(uint4*)(g_wkH + base) = hi;
    *(uint4*)(g_wkL + base) = lo;
}

// ===========================================================================
// Simple kernels
// ===========================================================================
__global__ void zero_weights_kernel() {
    int i = blockIdx.x * blockDim.x + threadIdx.x;
    if (i < N_B * T_S) g_weights[i] = 0.f;
}

// pq[n,u] = dot(q[n,:], Wq[u,:]) — warp owns u for ALL n; Wq read once.
// 128 blocks x 256 threads (8 warps). q chunk staged in smem.
__global__ void __launch_bounds__(256)
pq_kernel(const float* __restrict__ q, const float* __restrict__ Wq) {
    __shared__ float q_s[N_B][128];
    int tid  = threadIdx.x;
    int wid  = tid >> 5;
    int lane = tid & 31;
    int u    = blockIdx.x * 8 + wid;

    float acc[N_B];
    #pragma unroll
    for (int n = 0; n < N_B; n++) acc[n] = 0.f;

    for (int kc = 0; kc < D_E / 128; kc++) {
        // stage q[:, kc*128 : +128] -> smem (coalesced float4)
        __syncthreads();
        #pragma unroll
        for (int i = 0; i < 4; i++) {
            int flat4 = tid + i * 256;           // < 1024
            int n   = flat4 >> 5;
            int col = (flat4 & 31) * 4;
            *(float4*)&q_s[n][col] =
                *(const float4*)(q + (size_t)n * D_E + kc * 128 + col);
        }
        __syncthreads();

        float4 w = *(const float4*)(Wq + (size_t)u * D_E + kc * 128 + lane * 4);
        #pragma unroll
        for (int n = 0; n < N_B; n++) {
            float4 qv = *(const float4*)&q_s[n][lane * 4];
            acc[n] += qv.x * w.x + qv.y * w.y + qv.z * w.z + qv.w * w.w;
        }
    }
    #pragma unroll
    for (int n = 0; n < N_B; n++) {
        float s = acc[n];
        #pragma unroll
        for (int o = 16; o > 0; o >>= 1) s += __shfl_down_sync(0xffffffffu, s, o);
        if (lane == 0) g_pq[n * U_D + u] = s;
    }
}

__global__ void softmax_kernel(const int* __restrict__ lengths,
                               float* __restrict__ align) {
    int n   = blockIdx.x;
    int len = lengths[n];
    int tid = threadIdx.x;
    const float* w = g_weights + n * T_S;
    __shared__ float sm[256];

    float m = -1e30f;
    for (int t = tid; t < len; t += 256) m = fmaxf(m, w[t]);
    sm[tid] = m; __syncthreads();
    for (int s = 128; s > 0; s >>= 1) {
        if (tid < s) sm[tid] = fmaxf(sm[tid], sm[tid + s]);
        __syncthreads();
    }
    m = sm[0]; __syncthreads();

    float sum = 0.f;
    for (int t = tid; t < len; t += 256) sum += expf(w[t] - m);
    sm[tid] = sum; __syncthreads();
    for (int s = 128; s > 0; s >>= 1) {
        if (tid < s) sm[tid] += sm[tid + s];
        __syncthreads();
    }
    float inv = 1.f / sm[0];

    for (int t = tid; t < T_S; t += 256)
        align[(size_t)n * T_S + t] = (t < len) ? expf(w[t] - m) * inv : 0.f;
}

__global__ void context_kernel(const float* __restrict__ enc,
                               const int* __restrict__ lengths,
                               const float* __restrict__ align,
                               float* __restrict__ ctx) {
    int n   = blockIdx.y;
    int e   = blockIdx.x * 256 + threadIdx.x;
    int len = lengths[n];
    const float* al = align + (size_t)n * T_S;
    const float* E  = enc + (size_t)n * T_S * D_E + e;
    float c0 = 0.f, c1 = 0.f, c2 = 0.f, c3 = 0.f;
    int t = 0;
    for (; t + 4 <= len; t += 4) {
        c0 += al[t + 0] * E[(size_t)(t + 0) * D_E];
        c1 += al[t + 1] * E[(size_t)(t + 1) * D_E];
        c2 += al[t + 2] * E[(size_t)(t + 2) * D_E];
        c3 += al[t + 3] * E[(size_t)(t + 3) * D_E];
    }
    for (; t < len; t++) c0 += al[t] * E[(size_t)t * D_E];
    ctx[(size_t)n * D_E + e] = (c0 + c1) + (c2 + c3);
}

// ===========================================================================
// mma.sync 3xFP16-split fused logits GEMM — fragment-double-buffered mainloop
// ===========================================================================
#define BKF     64                    // fp32 K elems per chunk
#define NKC     (D_E / BKF)           // 16 chunks
#define OFF_AH  0
#define OFF_AL  16384
#define OFF_BH  32768
#define OFF_BL  49152
#define STAGE_B 65536
#define NST     3
#define DYN_SMEM (NST * STAGE_B)

__global__ void __launch_bounds__(512, 1)
weights_tc_kernel(const float* __restrict__ v, const int* __restrict__ lengths) {
    int n  = blockIdx.z;
    int t0 = blockIdx.y * 128;
    int u0 = blockIdx.x * 128;
    int len = lengths[n];
    if (t0 >= len) return;

    extern __shared__ char dyn_smem[];
    __shared__ float wpart[128];
    uint32_t base = smem_u32(dyn_smem);

    int tid  = threadIdx.x;
    int wid  = tid >> 5;
    int lane = tid & 31;
    int mr0 = (wid >> 2) * 32;
    int nc0 = (wid & 3) * 32;

    // ldmatrix per-thread geometry
    int rA  = lane & 15;
    int kgA = lane >> 4;
    int swA = rA & 7;
    int rB  = (lane & 7) | ((lane >> 4) << 3);
    int kgB = (lane >> 3) & 1;
    int swB = rB & 7;
    uint32_t rowA = (uint32_t)(mr0 + rA) * 128;   // byte offset within tile
    uint32_t rowB = (uint32_t)(nc0 + rB) * 128;

    // cp.async geometry
    int arow = tid >> 2;
    int g0   = (tid & 3) * 2;
    const __half* srcAH = g_encH + ((size_t)n * T_S + t0 + arow) * D_E + g0 * 8;
    const __half* srcAL = g_encL + ((size_t)n * T_S + t0 + arow) * D_E + g0 * 8;
    const __half* srcBH = g_wkH + ((size_t)(u0 + arow)) * D_E + g0 * 8;
    const __half* srcBL = g_wkL + ((size_t)(u0 + arow)) * D_E + g0 * 8;
    uint32_t d0 = base + (uint32_t)arow * 128 + (uint32_t)((g0 ^ (arow & 7)) << 4);
    uint32_t d1 = base + (uint32_t)arow * 128 + (uint32_t)(((g0 + 1) ^ (arow & 7)) << 4);

    float c[2][4][4];
    #pragma unroll
    for (int mi = 0; mi < 2; mi++)
        #pragma unroll
        for (int ni = 0; ni < 4; ni++)
            #pragma unroll
            for (int k = 0; k < 4; k++) c[mi][ni][k] = 0.f;

    // Double-buffered fragments
    uint32_t ah[2][2][4], al[2][2][4], bh[2][8], bl[2][8];

#define CP_STAGE(stg, kchunk) do {                                           \
        uint32_t _st = (uint32_t)(stg) * STAGE_B;                            \
        size_t _ko = (size_t)(kchunk) * BKF;                                 \
        cpasync16(d0 + _st + OFF_AH, srcAH + _ko);                           \
        cpasync16(d1 + _st + OFF_AH, srcAH + _ko + 8);                       \
        cpasync16(d0 + _st + OFF_AL, srcAL + _ko);                           \
        cpasync16(d1 + _st + OFF_AL, srcAL + _ko + 8);                       \
        cpasync16(d0 + _st + OFF_BH, srcBH + _ko);                           \
        cpasync16(d1 + _st + OFF_BH, srcBH + _ko + 8);                       \
        cpasync16(d0 + _st + OFF_BL, srcBL + _ko);                           \
        cpasync16(d1 + _st + OFF_BL, srcBL + _ko + 8);                       \
        cp_commit();                                                         \
    } while (0)

#define LOAD_FRAGS(buf, stg, ks) do {                                        \
        uint32_t _sb = base + (uint32_t)(stg) * STAGE_B;                     \
        uint32_t _gA = (uint32_t)((((ks) * 2 + kgA) ^ swA) << 4);            \
        uint32_t _gB = (uint32_t)((((ks) * 2 + kgB) ^ swB) << 4);            \
        uint32_t _aAH = _sb + OFF_AH + rowA;                                 \
        uint32_t _aAL = _sb + OFF_AL + rowA;                                 \
        uint32_t _aBH = _sb + OFF_BH + rowB;                                 \
        uint32_t _aBL = _sb + OFF_BL + rowB;                                 \
        ldm4(ah[buf][0], _aAH + _gA);                                        \
        ldm4(ah[buf][1], _aAH + 2048 + _gA);                                 \
        ldm4(al[buf][0], _aAL + _gA);                                        \
        ldm4(al[buf][1], _aAL + 2048 + _gA);                                 \
        ldm4(bh[buf] + 0, _aBH + _gB);                                       \
        ldm4(bh[buf] + 4, _aBH + 2048 + _gB);                                \
        ldm4(bl[buf] + 0, _aBL + _gB);                                       \
        ldm4(bl[buf] + 4, _aBL + 2048 + _gB);                                \
    } while (0)

#define MMA_STEP(buf) do {                                                   \
        _Pragma("unroll")                                                    \
        for (int mi = 0; mi < 2; mi++)                                       \
            _Pragma("unroll")                                                \
            for (int ni = 0; ni < 4; ni++) {                                 \
                mma16816(c[mi][ni], ah[buf][mi], bh[buf] + ni * 2);          \
                mma16816(c[mi][ni], ah[buf][mi], bl[buf] + ni * 2);          \
                mma16816(c[mi][ni], al[buf][mi], bh[buf] + ni * 2);          \
            }                                                                \
    } while (0)

    // ---- prologue: stages 0 and 1 in flight ----
    CP_STAGE(0, 0);
    CP_STAGE(1, 1);

    for (int kc = 0; kc < NKC; kc++) {
        asm volatile("cp.async.wait_group 0;" ::: "memory");
        __syncthreads();
        if (kc + 2 < NKC)
            CP_STAGE((kc + 2) % NST, kc + 2);

        int stg = kc % NST;
        if (kc == 0)
            LOAD_FRAGS(0, 0, 0);

        // ks=0
        LOAD_FRAGS(1, stg, 1);
        MMA_STEP(0);
        // ks=1
        LOAD_FRAGS(0, stg, 2);
        MMA_STEP(1);
        // ks=2
        LOAD_FRAGS(1, stg, 3);
        MMA_STEP(0);
        // ks=3 (prefetch next chunk's ks=0 across the barrier)
        if (kc + 1 < NKC)
            LOAD_FRAGS(0, (kc + 1) % NST, 0);
        MMA_STEP(1);
    }

    // ---- fused epilogue (HW tanh.approx) ----
    if (tid < 128) wpart[tid] = 0.f;
    __syncthreads();

    float vv[4][2], pqv[4][2];
    {
        const float* pqp = g_pq + (size_t)n * U_D + u0 + nc0;
        const float* vp  = v + u0 + nc0;
        #pragma unroll
        for (int ni = 0; ni < 4; ni++) {
            int cb = ni * 8 + 2 * (lane & 3);
            vv[ni][0] = vp[cb];     vv[ni][1] = vp[cb + 1];
            pqv[ni][0] = pqp[cb];   pqv[ni][1] = pqp[cb + 1];
        }
    }
    #pragma unroll
    for (int mi = 0; mi < 2; mi++) {
        float s1 = 0.f, s2 = 0.f;
        #pragma unroll
        for (int ni = 0; ni < 4; ni++) {
            s1 += vv[ni][0] * tanh_fast(c[mi][ni][0] + pqv[ni][0]);
            s1 += vv[ni][1] * tanh_fast(c[mi][ni][1] + pqv[ni][1]);
            s2 += vv[ni][0] * tanh_fast(c[mi][ni][2] + pqv[ni][0]);
            s2 += vv[ni][1] * tanh_fast(c[mi][ni][3] + pqv[ni][1]);
        }
        s1 += __shfl_xor_sync(0xffffffffu, s1, 1);
        s1 += __shfl_xor_sync(0xffffffffu, s1, 2);
        s2 += __shfl_xor_sync(0xffffffffu, s2, 1);
        s2 += __shfl_xor_sync(0xffffffffu, s2, 2);
        if ((lane & 3) == 0) {
            int r1 = mr0 + mi * 16 + (lane >> 2);
            atomicAdd(&wpart[r1], s1);
            atomicAdd(&wpart[r1 + 8], s2);
        }
    }
    __syncthreads();
    if (tid < 128 && (t0 + tid) < len)
        atomicAdd(&g_weights[n * T_S + t0 + tid], wpart[tid]);
}

// ===========================================================================
extern "C" void kernel_launch(void* const* d_in, const int* in_sizes, int n_in,
                              void* d_out, int out_size) {
    const float* q       = (const float*)d_in[0];  // [32,1,1024]
    const float* enc     = (const float*)d_in[1];  // [32,2048,1024]
    const int*   lengths = (const int*)  d_in[2];  // [32]
    const float* v       = (const float*)d_in[3];  // [1024]
    const float* Wq      = (const float*)d_in[4];  // [1024,1024]
    const float* Wk      = (const float*)d_in[5];  // [1024,1024]

    float* out   = (float*)d_out;
    float* ctx   = out;                 // contexts   [32,1024]
    float* align = out + N_B * D_E;     // alignments [32,2048]

    cudaFuncSetAttribute(weights_tc_kernel,
                         cudaFuncAttributeMaxDynamicSharedMemorySize, DYN_SMEM);

    zero_weights_kernel<<<(N_B * T_S + 255) / 256, 256>>>();
    convert_wk_kernel<<<512, 256>>>(Wk);
    convert_enc_kernel<<<dim3(T_S / 2, N_B), 256>>>(enc, lengths);
    pq_kernel<<<U_D / 8, 256>>>(q, Wq);

    dim3 g(U_D / 128, T_S / 128, N_B);   // u fastest for L2 reuse of enc tiles
    weights_tc_kernel<<<g, 512, DYN_SMEM>>>(v, lengths);

    softmax_kernel<<<N_B, 256>>>(lengths, align);

    dim3 gc(D_E / 256, N_B);
    context_kernel<<<gc, 256>>>(enc, lengths, align, ctx);
}

// round 9
// speedup vs baseline: 3.3044x; 1.5247x over previous
#include <cuda_runtime.h>
#include <cuda_fp16.h>
#include <cstdint>

#define N_B 32
#define T_S 2048
#define D_E 1024
#define U_D 1024

// Scratch (device globals: no allocation allowed)
__device__ float g_pq[2 * N_B * U_D];      // proj_query partials (k halves)
__device__ float g_weights[N_B * T_S];     // logits     [32,2048]
__device__ __half g_encH[N_B * T_S * D_E]; // enc hi fp16 (128MB)
__device__ __half g_encL[N_B * T_S * D_E]; // enc lo fp16 (128MB)
__device__ __half g_wkH[U_D * D_E];        // Wk hi fp16 (2MB)
__device__ __half g_wkL[U_D * D_E];        // Wk lo fp16 (2MB)

// ===========================================================================
// Helpers
// ===========================================================================
__device__ __forceinline__ uint32_t smem_u32(const void* p) {
    uint32_t a;
    asm("{ .reg .u64 t; cvta.to.shared.u64 t, %1; cvt.u32.u64 %0, t; }"
        : "=r"(a) : "l"(p));
    return a;
}
__device__ __forceinline__ void ldm4(uint32_t* r, uint32_t addr) {
    asm volatile("ldmatrix.sync.aligned.m8n8.x4.shared.b16 {%0,%1,%2,%3}, [%4];"
                 : "=r"(r[0]), "=r"(r[1]), "=r"(r[2]), "=r"(r[3]) : "r"(addr));
}
__device__ __forceinline__ void mma16816(float* c, const uint32_t* a,
                                         const uint32_t* b) {
    asm volatile(
        "mma.sync.aligned.m16n8k16.row.col.f32.f16.f16.f32 "
        "{%0,%1,%2,%3}, {%4,%5,%6,%7}, {%8,%9}, {%0,%1,%2,%3};"
        : "+f"(c[0]), "+f"(c[1]), "+f"(c[2]), "+f"(c[3])
        : "r"(a[0]), "r"(a[1]), "r"(a[2]), "r"(a[3]), "r"(b[0]), "r"(b[1]));
}
__device__ __forceinline__ void cpasync16(uint32_t dst, const void* src) {
    asm volatile("cp.async.cg.shared.global [%0], [%1], 16;"
                 :: "r"(dst), "l"(src) : "memory");
}
__device__ __forceinline__ void cp_commit() {
    asm volatile("cp.async.commit_group;" ::: "memory");
}
__device__ __forceinline__ float tanh_fast(float x) {
    float y;
    asm("tanh.approx.f32 %0, %1;" : "=f"(y) : "f"(x));
    return y;
}
__device__ __forceinline__ void split8(const float4 f0, const float4 f1,
                                       uint4& hi, uint4& lo) {
    __half2 h0 = __floats2half2_rn(f0.x, f0.y);
    __half2 h1 = __floats2half2_rn(f0.z, f0.w);
    __half2 h2 = __floats2half2_rn(f1.x, f1.y);
    __half2 h3 = __floats2half2_rn(f1.z, f1.w);
    float2 a0 = __half22float2(h0), a1 = __half22float2(h1);
    float2 a2 = __half22float2(h2), a3 = __half22float2(h3);
    __half2 l0 = __floats2half2_rn(f0.x - a0.x, f0.y - a0.y);
    __half2 l1 = __floats2half2_rn(f0.z - a1.x, f0.w - a1.y);
    __half2 l2 = __floats2half2_rn(f1.x - a2.x, f1.y - a2.y);
    __half2 l3 = __floats2half2_rn(f1.z - a3.x, f1.w - a3.y);
    hi = make_uint4(*(uint32_t*)&h0, *(uint32_t*)&h1, *(uint32_t*)&h2, *(uint32_t*)&h3);
    lo = make_uint4(*(uint32_t*)&l0, *(uint32_t*)&l1, *(uint32_t*)&l2, *(uint32_t*)&l3);
}

// ===========================================================================
// Fused prep kernel: convert_enc | pq | convert_wk | zero
// Block ranges:
//   [0, 32768)        convert_enc  (n = b>>10, t0 = (b&1023)*2)
//   [32768, 33024)    pq           (256 blocks; b&1 = k-half, 8 warps = 8 u)
//   [33024, 33536)    convert_wk
//   [33536, 33632)    zero g_weights + ctx
// ===========================================================================
#define PREP_ENC0   0
#define PREP_PQ0    32768
#define PREP_WK0    33024
#define PREP_ZERO0  33536
#define PREP_NBLK   33632

__global__ void __launch_bounds__(256)
prep_kernel(const float* __restrict__ enc, const float* __restrict__ q,
            const float* __restrict__ Wq, const float* __restrict__ Wk,
            const int* __restrict__ lengths, float* __restrict__ ctx) {
    __shared__ float q_s[N_B][128];
    int bid = blockIdx.x;
    int tid = threadIdx.x;

    if (bid < PREP_PQ0) {
        // ---- convert_enc: 2 rows per block ----
        int n  = bid >> 10;
        int t0 = (bid & 1023) * 2;
        int lenc = (lengths[n] + 127) & ~127;
        if (t0 >= lenc) return;
        size_t base = ((size_t)n * T_S + t0) * D_E + (size_t)tid * 8;
        float4 f0 = *(const float4*)(enc + base);
        float4 f1 = *(const float4*)(enc + base + 4);
        uint4 hi, lo;
        split8(f0, f1, hi, lo);
        *(uint4*)(g_encH + base) = hi;
        *(uint4*)(g_encL + base) = lo;
    } else if (bid < PREP_WK0) {
        // ---- pq: block owns 8 u values for one k-half ----
        int b    = bid - PREP_PQ0;          // 0..255
        int half = b & 1;
        int u    = (b >> 1) * 8 + (tid >> 5);
        int lane = tid & 31;
        int k0   = half * 512;

        float acc[N_B];
        #pragma unroll
        for (int n = 0; n < N_B; n++) acc[n] = 0.f;

        for (int kc = 0; kc < 4; kc++) {       // 4 chunks of 128 within half
            __syncthreads();
            #pragma unroll
            for (int i = 0; i < 4; i++) {
                int flat4 = tid + i * 256;      // < 1024
                int n   = flat4 >> 5;
                int col = (flat4 & 31) * 4;
                *(float4*)&q_s[n][col] =
                    *(const float4*)(q + (size_t)n * D_E + k0 + kc * 128 + col);
            }
            __syncthreads();
            float4 w = *(const float4*)(Wq + (size_t)u * D_E + k0 + kc * 128 + lane * 4);
            #pragma unroll
            for (int n = 0; n < N_B; n++) {
                float4 qv = *(const float4*)&q_s[n][lane * 4];
                acc[n] += qv.x * w.x + qv.y * w.y + qv.z * w.z + qv.w * w.w;
            }
        }
        #pragma unroll
        for (int n = 0; n < N_B; n++) {
            float s = acc[n];
            #pragma unroll
            for (int o = 16; o > 0; o >>= 1) s += __shfl_down_sync(0xffffffffu, s, o);
            if (lane == 0) g_pq[half * N_B * U_D + n * U_D + u] = s;
        }
    } else if (bid < PREP_ZERO0) {
        // ---- convert_wk ----
        size_t base = ((size_t)(bid - PREP_WK0) * 256 + tid) * 8;
        float4 f0 = *(const float4*)(Wk + base);
        float4 f1 = *(const float4*)(Wk + base + 4);
        uint4 hi, lo;
        split8(f0, f1, hi, lo);
        *(uint4*)(g_wkH + base) = hi;
        *(uint4*)(g_wkL + base) = lo;
    } else {
        // ---- zero g_weights (16384 float4) + ctx (8192 float4) ----
        int flat = (bid - PREP_ZERO0) * 256 + tid;   // < 24576
        if (flat < 16384)
            *(float4*)(g_weights + (size_t)flat * 4) = make_float4(0, 0, 0, 0);
        else
            *(float4*)(ctx + (size_t)(flat - 16384) * 4) = make_float4(0, 0, 0, 0);
    }
}

// ===========================================================================
// softmax (unchanged)
// ===========================================================================
__global__ void softmax_kernel(const int* __restrict__ lengths,
                               float* __restrict__ align) {
    int n   = blockIdx.x;
    int len = lengths[n];
    int tid = threadIdx.x;
    const float* w = g_weights + n * T_S;
    __shared__ float sm[256];

    float m = -1e30f;
    for (int t = tid; t < len; t += 256) m = fmaxf(m, w[t]);
    sm[tid] = m; __syncthreads();
    for (int s = 128; s > 0; s >>= 1) {
        if (tid < s) sm[tid] = fmaxf(sm[tid], sm[tid + s]);
        __syncthreads();
    }
    m = sm[0]; __syncthreads();

    float sum = 0.f;
    for (int t = tid; t < len; t += 256) sum += expf(w[t] - m);
    sm[tid] = sum; __syncthreads();
    for (int s = 128; s > 0; s >>= 1) {
        if (tid < s) sm[tid] += sm[tid + s];
        __syncthreads();
    }
    float inv = 1.f / sm[0];

    for (int t = tid; t < T_S; t += 256)
        align[(size_t)n * T_S + t] = (t < len) ? expf(w[t] - m) * inv : 0.f;
}

// ===========================================================================
// context: t-chunked partial sums, atomicAdd into zeroed ctx
// ===========================================================================
__global__ void context_kernel(const float* __restrict__ enc,
                               const int* __restrict__ lengths,
                               const float* __restrict__ align,
                               float* __restrict__ ctx) {
    int n   = blockIdx.y;
    int len = lengths[n];
    int tc  = blockIdx.z * 256;
    if (tc >= len) return;
    int te  = min(tc + 256, len);
    int e   = blockIdx.x * 256 + threadIdx.x;
    const float* al = align + (size_t)n * T_S;
    const float* E  = enc + ((size_t)n * T_S) * D_E + e;
    float c0 = 0.f, c1 = 0.f, c2 = 0.f, c3 = 0.f;
    int t = tc;
    for (; t + 4 <= te; t += 4) {
        c0 += al[t + 0] * E[(size_t)(t + 0) * D_E];
        c1 += al[t + 1] * E[(size_t)(t + 1) * D_E];
        c2 += al[t + 2] * E[(size_t)(t + 2) * D_E];
        c3 += al[t + 3] * E[(size_t)(t + 3) * D_E];
    }
    for (; t < te; t++) c0 += al[t] * E[(size_t)t * D_E];
    atomicAdd(&ctx[(size_t)n * D_E + e], (c0 + c1) + (c2 + c3));
}

// ===========================================================================
// mma.sync 3xFP16-split fused logits GEMM — fragment-double-buffered mainloop
// ===========================================================================
#define BKF     64                    // fp32 K elems per chunk
#define NKC     (D_E / BKF)           // 16 chunks
#define OFF_AH  0
#define OFF_AL  16384
#define OFF_BH  32768
#define OFF_BL  49152
#define STAGE_B 65536
#define NST     3
#define DYN_SMEM (NST * STAGE_B)

__global__ void __launch_bounds__(512, 1)
weights_tc_kernel(const float* __restrict__ v, const int* __restrict__ lengths) {
    int n  = blockIdx.z;
    int t0 = blockIdx.y * 128;
    int u0 = blockIdx.x * 128;
    int len = lengths[n];
    if (t0 >= len) return;

    extern __shared__ char dyn_smem[];
    __shared__ float wpart[128];
    uint32_t base = smem_u32(dyn_smem);

    int tid  = threadIdx.x;
    int wid  = tid >> 5;
    int lane = tid & 31;
    int mr0 = (wid >> 2) * 32;
    int nc0 = (wid & 3) * 32;

    // ldmatrix per-thread geometry
    int rA  = lane & 15;
    int kgA = lane >> 4;
    int swA = rA & 7;
    int rB  = (lane & 7) | ((lane >> 4) << 3);
    int kgB = (lane >> 3) & 1;
    int swB = rB & 7;
    uint32_t rowA = (uint32_t)(mr0 + rA) * 128;
    uint32_t rowB = (uint32_t)(nc0 + rB) * 128;

    // cp.async geometry
    int arow = tid >> 2;
    int g0   = (tid & 3) * 2;
    const __half* srcAH = g_encH + ((size_t)n * T_S + t0 + arow) * D_E + g0 * 8;
    const __half* srcAL = g_encL + ((size_t)n * T_S + t0 + arow) * D_E + g0 * 8;
    const __half* srcBH = g_wkH + ((size_t)(u0 + arow)) * D_E + g0 * 8;
    const __half* srcBL = g_wkL + ((size_t)(u0 + arow)) * D_E + g0 * 8;
    uint32_t d0 = base + (uint32_t)arow * 128 + (uint32_t)((g0 ^ (arow & 7)) << 4);
    uint32_t d1 = base + (uint32_t)arow * 128 + (uint32_t)(((g0 + 1) ^ (arow & 7)) << 4);

    float c[2][4][4];
    #pragma unroll
    for (int mi = 0; mi < 2; mi++)
        #pragma unroll
        for (int ni = 0; ni < 4; ni++)
            #pragma unroll
            for (int k = 0; k < 4; k++) c[mi][ni][k] = 0.f;

    uint32_t ah[2][2][4], al[2][2][4], bh[2][8], bl[2][8];

#define CP_STAGE(stg, kchunk) do {                                           \
        uint32_t _st = (uint32_t)(stg) * STAGE_B;                            \
        size_t _ko = (size_t)(kchunk) * BKF;                                 \
        cpasync16(d0 + _st + OFF_AH, srcAH + _ko);                           \
        cpasync16(d1 + _st + OFF_AH, srcAH + _ko + 8);                       \
        cpasync16(d0 + _st + OFF_AL, srcAL + _ko);                           \
        cpasync16(d1 + _st + OFF_AL, srcAL + _ko + 8);                       \
        cpasync16(d0 + _st + OFF_BH, srcBH + _ko);                           \
        cpasync16(d1 + _st + OFF_BH, srcBH + _ko + 8);                       \
        cpasync16(d0 + _st + OFF_BL, srcBL + _ko);                           \
        cpasync16(d1 + _st + OFF_BL, srcBL + _ko + 8);                       \
        cp_commit();                                                         \
    } while (0)

#define LOAD_FRAGS(buf, stg, ks) do {                                        \
        uint32_t _sb = base + (uint32_t)(stg) * STAGE_B;                     \
        uint32_t _gA = (uint32_t)((((ks) * 2 + kgA) ^ swA) << 4);            \
        uint32_t _gB = (uint32_t)((((ks) * 2 + kgB) ^ swB) << 4);            \
        uint32_t _aAH = _sb + OFF_AH + rowA;                                 \
        uint32_t _aAL = _sb + OFF_AL + rowA;                                 \
        uint32_t _aBH = _sb + OFF_BH + rowB;                                 \
        uint32_t _aBL = _sb + OFF_BL + rowB;                                 \
        ldm4(ah[buf][0], _aAH + _gA);                                        \
        ldm4(ah[buf][1], _aAH + 2048 + _gA);                                 \
        ldm4(al[buf][0], _aAL + _gA);                                        \
        ldm4(al[buf][1], _aAL + 2048 + _gA);                                 \
        ldm4(bh[buf] + 0, _aBH + _gB);                                       \
        ldm4(bh[buf] + 4, _aBH + 2048 + _gB);                                \
        ldm4(bl[buf] + 0, _aBL + _gB);                                       \
        ldm4(bl[buf] + 4, _aBL + 2048 + _gB);                                \
    } while (0)

#define MMA_STEP(buf) do {                                                   \
        _Pragma("unroll")                                                    \
        for (int mi = 0; mi < 2; mi++)                                       \
            _Pragma("unroll")                                                \
            for (int ni = 0; ni < 4; ni++) {                                 \
                mma16816(c[mi][ni], ah[buf][mi], bh[buf] + ni * 2);          \
                mma16816(c[mi][ni], ah[buf][mi], bl[buf] + ni * 2);          \
                mma16816(c[mi][ni], al[buf][mi], bh[buf] + ni * 2);          \
            }                                                                \
    } while (0)

    CP_STAGE(0, 0);
    CP_STAGE(1, 1);

    for (int kc = 0; kc < NKC; kc++) {
        asm volatile("cp.async.wait_group 0;" ::: "memory");
        __syncthreads();
        if (kc + 2 < NKC)
            CP_STAGE((kc + 2) % NST, kc + 2);

        int stg = kc % NST;
        if (kc == 0)
            LOAD_FRAGS(0, 0, 0);

        LOAD_FRAGS(1, stg, 1);
        MMA_STEP(0);
        LOAD_FRAGS(0, stg, 2);
        MMA_STEP(1);
        LOAD_FRAGS(1, stg, 3);
        MMA_STEP(0);
        if (kc + 1 < NKC)
            LOAD_FRAGS(0, (kc + 1) % NST, 0);
        MMA_STEP(1);
    }

    // ---- fused epilogue (HW tanh.approx; pq = sum of two k-half partials) ----
    if (tid < 128) wpart[tid] = 0.f;
    __syncthreads();

    float vv[4][2], pqv[4][2];
    {
        const float* pqp = g_pq + (size_t)n * U_D + u0 + nc0;
        const float* vp  = v + u0 + nc0;
        #pragma unroll
        for (int ni = 0; ni < 4; ni++) {
            int cb = ni * 8 + 2 * (lane & 3);
            vv[ni][0] = vp[cb];     vv[ni][1] = vp[cb + 1];
            pqv[ni][0] = pqp[cb] + pqp[N_B * U_D + cb];
            pqv[ni][1] = pqp[cb + 1] + pqp[N_B * U_D + cb + 1];
        }
    }
    #pragma unroll
    for (int mi = 0; mi < 2; mi++) {
        float s1 = 0.f, s2 = 0.f;
        #pragma unroll
        for (int ni = 0; ni < 4; ni++) {
            s1 += vv[ni][0] * tanh_fast(c[mi][ni][0] + pqv[ni][0]);
            s1 += vv[ni][1] * tanh_fast(c[mi][ni][1] + pqv[ni][1]);
            s2 += vv[ni][0] * tanh_fast(c[mi][ni][2] + pqv[ni][0]);
            s2 += vv[ni][1] * tanh_fast(c[mi][ni][3] + pqv[ni][1]);
        }
        s1 += __shfl_xor_sync(0xffffffffu, s1, 1);
        s1 += __shfl_xor_sync(0xffffffffu, s1, 2);
        s2 += __shfl_xor_sync(0xffffffffu, s2, 1);
        s2 += __shfl_xor_sync(0xffffffffu, s2, 2);
        if ((lane & 3) == 0) {
            int r1 = mr0 + mi * 16 + (lane >> 2);
            atomicAdd(&wpart[r1], s1);
            atomicAdd(&wpart[r1 + 8], s2);
        }
    }
    __syncthreads();
    if (tid < 128 && (t0 + tid) < len)
        atomicAdd(&g_weights[n * T_S + t0 + tid], wpart[tid]);
}

// ===========================================================================
extern "C" void kernel_launch(void* const* d_in, const int* in_sizes, int n_in,
                              void* d_out, int out_size) {
    const float* q       = (const float*)d_in[0];  // [32,1,1024]
    const float* enc     = (const float*)d_in[1];  // [32,2048,1024]
    const int*   lengths = (const int*)  d_in[2];  // [32]
    const float* v       = (const float*)d_in[3];  // [1024]
    const float* Wq      = (const float*)d_in[4];  // [1024,1024]
    const float* Wk      = (const float*)d_in[5];  // [1024,1024]

    float* out   = (float*)d_out;
    float* ctx   = out;                 // contexts   [32,1024]
    float* align = out + N_B * D_E;     // alignments [32,2048]

    cudaFuncSetAttribute(weights_tc_kernel,
                         cudaFuncAttributeMaxDynamicSharedMemorySize, DYN_SMEM);

    prep_kernel<<<PREP_NBLK, 256>>>(enc, q, Wq, Wk, lengths, ctx);

    dim3 g(U_D / 128, T_S / 128, N_B);   // u fastest for L2 reuse of enc tiles
    weights_tc_kernel<<<g, 512, DYN_SMEM>>>(v, lengths);

    softmax_kernel<<<N_B, 256>>>(lengths, align);

    dim3 gc(D_E / 256, N_B, T_S / 256);
    context_kernel<<<gc, 256>>>(enc, lengths, align, ctx);
}

// round 12
// speedup vs baseline: 3.4061x; 1.0308x over previous
#include <cuda_runtime.h>
#include <cuda_fp16.h>
#include <cstdint>

#define N_B 32
#define T_S 2048
#define D_E 1024
#define U_D 1024

// Scratch (device globals: no allocation allowed)
__device__ float g_pq[2 * N_B * U_D];      // proj_query partials (k halves)
__device__ float g_weights[N_B * T_S];     // logits     [32,2048]
__device__ __half g_encH[N_B * T_S * D_E]; // enc hi fp16 (128MB)
__device__ __half g_encL[N_B * T_S * D_E]; // enc lo fp16 (128MB)
__device__ __half g_wkH[U_D * D_E];        // Wk hi fp16 (2MB)
__device__ __half g_wkL[U_D * D_E];        // Wk lo fp16 (2MB)

// ===========================================================================
// Helpers
// ===========================================================================
__device__ __forceinline__ uint32_t smem_u32(const void* p) {
    uint32_t a;
    asm("{ .reg .u64 t; cvta.to.shared.u64 t, %1; cvt.u32.u64 %0, t; }"
        : "=r"(a) : "l"(p));
    return a;
}
__device__ __forceinline__ void ldm4(uint32_t* r, uint32_t addr) {
    asm volatile("ldmatrix.sync.aligned.m8n8.x4.shared.b16 {%0,%1,%2,%3}, [%4];"
                 : "=r"(r[0]), "=r"(r[1]), "=r"(r[2]), "=r"(r[3]) : "r"(addr));
}
__device__ __forceinline__ void mma16816(float* c, const uint32_t* a,
                                         const uint32_t* b) {
    asm volatile(
        "mma.sync.aligned.m16n8k16.row.col.f32.f16.f16.f32 "
        "{%0,%1,%2,%3}, {%4,%5,%6,%7}, {%8,%9}, {%0,%1,%2,%3};"
        : "+f"(c[0]), "+f"(c[1]), "+f"(c[2]), "+f"(c[3])
        : "r"(a[0]), "r"(a[1]), "r"(a[2]), "r"(a[3]), "r"(b[0]), "r"(b[1]));
}
__device__ __forceinline__ void cpasync16(uint32_t dst, const void* src) {
    asm volatile("cp.async.cg.shared.global [%0], [%1], 16;"
                 :: "r"(dst), "l"(src) : "memory");
}
__device__ __forceinline__ void cp_commit() {
    asm volatile("cp.async.commit_group;" ::: "memory");
}
__device__ __forceinline__ float tanh_fast(float x) {
    float y;
    asm("tanh.approx.f32 %0, %1;" : "=f"(y) : "f"(x));
    return y;
}
__device__ __forceinline__ void split8(const float4 f0, const float4 f1,
                                       uint4& hi, uint4& lo) {
    __half2 h0 = __floats2half2_rn(f0.x, f0.y);
    __half2 h1 = __floats2half2_rn(f0.z, f0.w);
    __half2 h2 = __floats2half2_rn(f1.x, f1.y);
    __half2 h3 = __floats2half2_rn(f1.z, f1.w);
    float2 a0 = __half22float2(h0), a1 = __half22float2(h1);
    float2 a2 = __half22float2(h2), a3 = __half22float2(h3);
    __half2 l0 = __floats2half2_rn(f0.x - a0.x, f0.y - a0.y);
    __half2 l1 = __floats2half2_rn(f0.z - a1.x, f0.w - a1.y);
    __half2 l2 = __floats2half2_rn(f1.x - a2.x, f1.y - a2.y);
    __half2 l3 = __floats2half2_rn(f1.z - a3.x, f1.w - a3.y);
    hi = make_uint4(*(uint32_t*)&h0, *(uint32_t*)&h1, *(uint32_t*)&h2, *(uint32_t*)&h3);
    lo = make_uint4(*(uint32_t*)&l0, *(uint32_t*)&l1, *(uint32_t*)&l2, *(uint32_t*)&l3);
}

// ===========================================================================
// Fused prep kernel: convert_enc | pq | convert_wk | zero
// ===========================================================================
#define PREP_ENC0   0
#define PREP_PQ0    32768
#define PREP_WK0    33024
#define PREP_ZERO0  33536
#define PREP_NBLK   33632

__global__ void __launch_bounds__(256)
prep_kernel(const float* __restrict__ enc, const float* __restrict__ q,
            const float* __restrict__ Wq, const float* __restrict__ Wk,
            const int* __restrict__ lengths, float* __restrict__ ctx) {
    __shared__ float q_s[N_B][128];
    int bid = blockIdx.x;
    int tid = threadIdx.x;

    if (bid < PREP_PQ0) {
        int n  = bid >> 10;
        int t0 = (bid & 1023) * 2;
        int lenc = (lengths[n] + 127) & ~127;
        if (t0 >= lenc) return;
        size_t base = ((size_t)n * T_S + t0) * D_E + (size_t)tid * 8;
        float4 f0 = *(const float4*)(enc + base);
        float4 f1 = *(const float4*)(enc + base + 4);
        uint4 hi, lo;
        split8(f0, f1, hi, lo);
        *(uint4*)(g_encH + base) = hi;
        *(uint4*)(g_encL + base) = lo;
    } else if (bid < PREP_WK0) {
        int b    = bid - PREP_PQ0;          // 0..255
        int half = b & 1;
        int u    = (b >> 1) * 8 + (tid >> 5);
        int lane = tid & 31;
        int k0   = half * 512;

        float acc[N_B];
        #pragma unroll
        for (int n = 0; n < N_B; n++) acc[n] = 0.f;

        for (int kc = 0; kc < 4; kc++) {
            __syncthreads();
            #pragma unroll
            for (int i = 0; i < 4; i++) {
                int flat4 = tid + i * 256;
                int n   = flat4 >> 5;
                int col = (flat4 & 31) * 4;
                *(float4*)&q_s[n][col] =
                    *(const float4*)(q + (size_t)n * D_E + k0 + kc * 128 + col);
            }
            __syncthreads();
            float4 w = *(const float4*)(Wq + (size_t)u * D_E + k0 + kc * 128 + lane * 4);
            #pragma unroll
            for (int n = 0; n < N_B; n++) {
                float4 qv = *(const float4*)&q_s[n][lane * 4];
                acc[n] += qv.x * w.x + qv.y * w.y + qv.z * w.z + qv.w * w.w;
            }
        }
        #pragma unroll
        for (int n = 0; n < N_B; n++) {
            float s = acc[n];
            #pragma unroll
            for (int o = 16; o > 0; o >>= 1) s += __shfl_down_sync(0xffffffffu, s, o);
            if (lane == 0) g_pq[half * N_B * U_D + n * U_D + u] = s;
        }
    } else if (bid < PREP_ZERO0) {
        size_t base = ((size_t)(bid - PREP_WK0) * 256 + tid) * 8;
        float4 f0 = *(const float4*)(Wk + base);
        float4 f1 = *(const float4*)(Wk + base + 4);
        uint4 hi, lo;
        split8(f0, f1, hi, lo);
        *(uint4*)(g_wkH + base) = hi;
        *(uint4*)(g_wkL + base) = lo;
    } else {
        int flat = (bid - PREP_ZERO0) * 256 + tid;   // < 24576
        if (flat < 16384)
            *(float4*)(g_weights + (size_t)flat * 4) = make_float4(0, 0, 0, 0);
        else
            *(float4*)(ctx + (size_t)(flat - 16384) * 4) = make_float4(0, 0, 0, 0);
    }
}

// ===========================================================================
// Fused softmax + context:
//   Every block recomputes row softmax stats from g_weights (L2-resident).
//   Blocks with bx==0 write align for their 128-t chunk (zeros when masked).
//   All blocks accumulate ctx partials over their t-chunk with 8-way MLP.
//   grid = (D_E/256, N_B, T_S/128)
// ===========================================================================
__global__ void __launch_bounds__(256)
sm_context_kernel(const float* __restrict__ enc,
                  const int* __restrict__ lengths,
                  float* __restrict__ align, float* __restrict__ ctx) {
    int n    = blockIdx.y;
    int len  = lengths[n];
    int tc   = blockIdx.z * 128;
    bool wr  = (blockIdx.x == 0);
    if (!wr && tc >= len) return;

    int tid = threadIdx.x;
    const float* w = g_weights + (size_t)n * T_S;
    __shared__ float sm[256];

    // ---- softmax stats over [0, len) ----
    float m = -1e30f;
    for (int t = tid; t < len; t += 256) m = fmaxf(m, w[t]);
    sm[tid] = m; __syncthreads();
    #pragma unroll
    for (int s = 128; s > 0; s >>= 1) {
        if (tid < s) sm[tid] = fmaxf(sm[tid], sm[tid + s]);
        __syncthreads();
    }
    m = sm[0]; __syncthreads();

    float sum = 0.f;
    for (int t = tid; t < len; t += 256) sum += __expf(w[t] - m);
    sm[tid] = sum; __syncthreads();
    #pragma unroll
    for (int s = 128; s > 0; s >>= 1) {
        if (tid < s) sm[tid] += sm[tid + s];
        __syncthreads();
    }
    float inv = 1.f / sm[0];

    // ---- align writer (bx == 0): 128 t per block, half per thread-pair ----
    if (wr) {
        #pragma unroll
        for (int i = 0; i < 128; i += 256 / 2) { }  // (unrolled below)
        // 256 threads cover 128 t twice over; just let threads 0..127 do it
        if (tid < 128) {
            int t = tc + tid;
            align[(size_t)n * T_S + t] = (t < len) ? __expf(w[t] - m) * inv : 0.f;
        }
        if (tc >= len) return;
    }

    // ---- context accumulation over [tc, te) with 8 independent chains ----
    int te = min(tc + 128, len);
    int e  = blockIdx.x * 256 + tid;
    const float* E = enc + ((size_t)n * T_S) * D_E + e;

    float a[8];
    float c0 = 0.f, c1 = 0.f, c2 = 0.f, c3 = 0.f;
    float c4 = 0.f, c5 = 0.f, c6 = 0.f, c7 = 0.f;
    int t = tc;
    for (; t + 8 <= te; t += 8) {
        #pragma unroll
        for (int j = 0; j < 8; j++) a[j] = __expf(w[t + j] - m) * inv;
        c0 += a[0] * E[(size_t)(t + 0) * D_E];
        c1 += a[1] * E[(size_t)(t + 1) * D_E];
        c2 += a[2] * E[(size_t)(t + 2) * D_E];
        c3 += a[3] * E[(size_t)(t + 3) * D_E];
        c4 += a[4] * E[(size_t)(t + 4) * D_E];
        c5 += a[5] * E[(size_t)(t + 5) * D_E];
        c6 += a[6] * E[(size_t)(t + 6) * D_E];
        c7 += a[7] * E[(size_t)(t + 7) * D_E];
    }
    for (; t < te; t++) c0 += __expf(w[t] - m) * inv * E[(size_t)t * D_E];
    float tot = ((c0 + c1) + (c2 + c3)) + ((c4 + c5) + (c6 + c7));
    atomicAdd(&ctx[(size_t)n * D_E + e], tot);
}

// ===========================================================================
// mma.sync 3xFP16-split fused logits GEMM — fragment-double-buffered mainloop
// ===========================================================================
#define BKF     64                    // fp32 K elems per chunk
#define NKC     (D_E / BKF)           // 16 chunks
#define OFF_AH  0
#define OFF_AL  16384
#define OFF_BH  32768
#define OFF_BL  49152
#define STAGE_B 65536
#define NST     3
#define DYN_SMEM (NST * STAGE_B)

__global__ void __launch_bounds__(512, 1)
weights_tc_kernel(const float* __restrict__ v, const int* __restrict__ lengths) {
    int n  = blockIdx.z;
    int t0 = blockIdx.y * 128;
    int u0 = blockIdx.x * 128;
    int len = lengths[n];
    if (t0 >= len) return;

    extern __shared__ char dyn_smem[];
    __shared__ float wpart[128];
    uint32_t base = smem_u32(dyn_smem);

    int tid  = threadIdx.x;
    int wid  = tid >> 5;
    int lane = tid & 31;
    int mr0 = (wid >> 2) * 32;
    int nc0 = (wid & 3) * 32;

    int rA  = lane & 15;
    int kgA = lane >> 4;
    int swA = rA & 7;
    int rB  = (lane & 7) | ((lane >> 4) << 3);
    int kgB = (lane >> 3) & 1;
    int swB = rB & 7;
    uint32_t rowA = (uint32_t)(mr0 + rA) * 128;
    uint32_t rowB = (uint32_t)(nc0 + rB) * 128;

    int arow = tid >> 2;
    int g0   = (tid & 3) * 2;
    const __half* srcAH = g_encH + ((size_t)n * T_S + t0 + arow) * D_E + g0 * 8;
    const __half* srcAL = g_encL + ((size_t)n * T_S + t0 + arow) * D_E + g0 * 8;
    const __half* srcBH = g_wkH + ((size_t)(u0 + arow)) * D_E + g0 * 8;
    const __half* srcBL = g_wkL + ((size_t)(u0 + arow)) * D_E + g0 * 8;
    uint32_t d0 = base + (uint32_t)arow * 128 + (uint32_t)((g0 ^ (arow & 7)) << 4);
    uint32_t d1 = base + (uint32_t)arow * 128 + (uint32_t)(((g0 + 1) ^ (arow & 7)) << 4);

    float c[2][4][4];
    #pragma unroll
    for (int mi = 0; mi < 2; mi++)
        #pragma unroll
        for (int ni = 0; ni < 4; ni++)
            #pragma unroll
            for (int k = 0; k < 4; k++) c[mi][ni][k] = 0.f;

    uint32_t ah[2][2][4], al[2][2][4], bh[2][8], bl[2][8];

#define CP_STAGE(stg, kchunk) do {                                           \
        uint32_t _st = (uint32_t)(stg) * STAGE_B;                            \
        size_t _ko = (size_t)(kchunk) * BKF;                                 \
        cpasync16(d0 + _st + OFF_AH, srcAH + _ko);                           \
        cpasync16(d1 + _st + OFF_AH, srcAH + _ko + 8);                       \
        cpasync16(d0 + _st + OFF_AL, srcAL + _ko);                           \
        cpasync16(d1 + _st + OFF_AL, srcAL + _ko + 8);                       \
        cpasync16(d0 + _st + OFF_BH, srcBH + _ko);                           \
        cpasync16(d1 + _st + OFF_BH, srcBH + _ko + 8);                       \
        cpasync16(d0 + _st + OFF_BL, srcBL + _ko);                           \
        cpasync16(d1 + _st + OFF_BL, srcBL + _ko + 8);                       \
        cp_commit();                                                         \
    } while (0)

#define LOAD_FRAGS(buf, stg, ks) do {                                        \
        uint32_t _sb = base + (uint32_t)(stg) * STAGE_B;                     \
        uint32_t _gA = (uint32_t)((((ks) * 2 + kgA) ^ swA) << 4);            \
        uint32_t _gB = (uint32_t)((((ks) * 2 + kgB) ^ swB) << 4);            \
        uint32_t _aAH = _sb + OFF_AH + rowA;                                 \
        uint32_t _aAL = _sb + OFF_AL + rowA;                                 \
        uint32_t _aBH = _sb + OFF_BH + rowB;                                 \
        uint32_t _aBL = _sb + OFF_BL + rowB;                                 \
        ldm4(ah[buf][0], _aAH + _gA);                                        \
        ldm4(ah[buf][1], _aAH + 2048 + _gA);                                 \
        ldm4(al[buf][0], _aAL + _gA);                                        \
        ldm4(al[buf][1], _aAL + 2048 + _gA);                                 \
        ldm4(bh[buf] + 0, _aBH + _gB);                                       \
        ldm4(bh[buf] + 4, _aBH + 2048 + _gB);                                \
        ldm4(bl[buf] + 0, _aBL + _gB);                                       \
        ldm4(bl[buf] + 4, _aBL + 2048 + _gB);                                \
    } while (0)

#define MMA_STEP(buf) do {                                                   \
        _Pragma("unroll")                                                    \
        for (int mi = 0; mi < 2; mi++)                                       \
            _Pragma("unroll")                                                \
            for (int ni = 0; ni < 4; ni++) {                                 \
                mma16816(c[mi][ni], ah[buf][mi], bh[buf] + ni * 2);          \
                mma16816(c[mi][ni], ah[buf][mi], bl[buf] + ni * 2);          \
                mma16816(c[mi][ni], al[buf][mi], bh[buf] + ni * 2);          \
            }                                                                \
    } while (0)

    CP_STAGE(0, 0);
    CP_STAGE(1, 1);

    for (int kc = 0; kc < NKC; kc++) {
        asm volatile("cp.async.wait_group 0;" ::: "memory");
        __syncthreads();
        if (kc + 2 < NKC)
            CP_STAGE((kc + 2) % NST, kc + 2);

        int stg = kc % NST;
        if (kc == 0)
            LOAD_FRAGS(0, 0, 0);

        LOAD_FRAGS(1, stg, 1);
        MMA_STEP(0);
        LOAD_FRAGS(0, stg, 2);
        MMA_STEP(1);
        LOAD_FRAGS(1, stg, 3);
        MMA_STEP(0);
        if (kc + 1 < NKC)
            LOAD_FRAGS(0, (kc + 1) % NST, 0);
        MMA_STEP(1);
    }

    // ---- fused epilogue (HW tanh.approx; pq = sum of two k-half partials) ----
    if (tid < 128) wpart[tid] = 0.f;
    __syncthreads();

    float vv[4][2], pqv[4][2];
    {
        const float* pqp = g_pq + (size_t)n * U_D + u0 + nc0;
        const float* vp  = v + u0 + nc0;
        #pragma unroll
        for (int ni = 0; ni < 4; ni++) {
            int cb = ni * 8 + 2 * (lane & 3);
            vv[ni][0] = vp[cb];     vv[ni][1] = vp[cb + 1];
            pqv[ni][0] = pqp[cb] + pqp[N_B * U_D + cb];
            pqv[ni][1] = pqp[cb + 1] + pqp[N_B * U_D + cb + 1];
        }
    }
    #pragma unroll
    for (int mi = 0; mi < 2; mi++) {
        float s1 = 0.f, s2 = 0.f;
        #pragma unroll
        for (int ni = 0; ni < 4; ni++) {
            s1 += vv[ni][0] * tanh_fast(c[mi][ni][0] + pqv[ni][0]);
            s1 += vv[ni][1] * tanh_fast(c[mi][ni][1] + pqv[ni][1]);
            s2 += vv[ni][0] * tanh_fast(c[mi][ni][2] + pqv[ni][0]);
            s2 += vv[ni][1] * tanh_fast(c[mi][ni][3] + pqv[ni][1]);
        }
        s1 += __shfl_xor_sync(0xffffffffu, s1, 1);
        s1 += __shfl_xor_sync(0xffffffffu, s1, 2);
        s2 += __shfl_xor_sync(0xffffffffu, s2, 1);
        s2 += __shfl_xor_sync(0xffffffffu, s2, 2);
        if ((lane & 3) == 0) {
            int r1 = mr0 + mi * 16 + (lane >> 2);
            atomicAdd(&wpart[r1], s1);
            atomicAdd(&wpart[r1 + 8], s2);
        }
    }
    __syncthreads();
    if (tid < 128 && (t0 + tid) < len)
        atomicAdd(&g_weights[n * T_S + t0 + tid], wpart[tid]);
}

// ===========================================================================
extern "C" void kernel_launch(void* const* d_in, const int* in_sizes, int n_in,
                              void* d_out, int out_size) {
    const float* q       = (const float*)d_in[0];  // [32,1,1024]
    const float* enc     = (const float*)d_in[1];  // [32,2048,1024]
    const int*   lengths = (const int*)  d_in[2];  // [32]
    const float* v       = (const float*)d_in[3];  // [1024]
    const float* Wq      = (const float*)d_in[4];  // [1024,1024]
    const float* Wk      = (const float*)d_in[5];  // [1024,1024]

    float* out   = (float*)d_out;
    float* ctx   = out;                 // contexts   [32,1024]
    float* align = out + N_B * D_E;     // alignments [32,2048]

    cudaFuncSetAttribute(weights_tc_kernel,
                         cudaFuncAttributeMaxDynamicSharedMemorySize, DYN_SMEM);

    prep_kernel<<<PREP_NBLK, 256>>>(enc, q, Wq, Wk, lengths, ctx);

    dim3 g(U_D / 128, T_S / 128, N_B);   // u fastest for L2 reuse of enc tiles
    weights_tc_kernel<<<g, 512, DYN_SMEM>>>(v, lengths);

    dim3 gc(D_E / 256, N_B, T_S / 128);
    sm_context_kernel<<<gc, 256>>>(enc, lengths, align, ctx);
}